// round 1
// baseline (speedup 1.0000x reference)
#include <cuda_runtime.h>
#include <math.h>

#define Bq  2
#define Tq  1024
#define Hh  8
#define Dd  128
#define HIDN 1024
#define BT  (Bq*Tq)

// ---------------- scratch (device globals; no allocation allowed) ----------------
__device__ float g_qpre[BT*HIDN];
__device__ float g_kpre[BT*HIDN];
__device__ float g_vpre[BT*HIDN];
__device__ float g_qn[BT*HIDN];
__device__ float g_kn[BT*HIDN];
__device__ float g_vn[BT*HIDN];
__device__ float g_fa[BT*Dd];
__device__ float g_gbuf[BT*HIDN];
__device__ float g_betab[BT*Hh];
__device__ float g_gab[BT*Dd];
__device__ float g_gateb[BT*HIDN];
__device__ float g_attn[BT*HIDN];

// ---------------- generic fp32 GEMM: C[M,N] = A[M,K] * B[N,K]^T ----------------
#define GBM 64
#define GBN 64
#define GBK 16
__global__ void gemm_nt(const float* __restrict__ A, const float* __restrict__ Bm,
                        float* __restrict__ C, int M, int N, int K) {
    __shared__ float As[GBK][GBM + 1];
    __shared__ float Bs[GBK][GBN + 1];
    int tid = threadIdx.x;
    int tx = tid & 15, ty = tid >> 4;
    int bm = blockIdx.y * GBM, bn = blockIdx.x * GBN;
    float acc[4][4];
#pragma unroll
    for (int i = 0; i < 4; i++)
#pragma unroll
        for (int j = 0; j < 4; j++) acc[i][j] = 0.f;

    for (int k0 = 0; k0 < K; k0 += GBK) {
        int col = tid & 15;
#pragma unroll
        for (int r0 = 0; r0 < GBM; r0 += 16) {
            int r = r0 + (tid >> 4);
            // M is always a multiple of 64 here (2048); rows of A always valid
            As[col][r] = A[(size_t)(bm + r) * K + k0 + col];
            Bs[col][r] = (bn + r < N) ? Bm[(size_t)(bn + r) * K + k0 + col] : 0.f;
        }
        __syncthreads();
#pragma unroll
        for (int kk = 0; kk < GBK; kk++) {
            float ra[4], rb[4];
#pragma unroll
            for (int i = 0; i < 4; i++) ra[i] = As[kk][ty * 4 + i];
#pragma unroll
            for (int j = 0; j < 4; j++) rb[j] = Bs[kk][tx * 4 + j];
#pragma unroll
            for (int i = 0; i < 4; i++)
#pragma unroll
                for (int j = 0; j < 4; j++)
                    acc[i][j] += ra[i] * rb[j];
        }
        __syncthreads();
    }
#pragma unroll
    for (int i = 0; i < 4; i++) {
        int m = bm + ty * 4 + i;
#pragma unroll
        for (int j = 0; j < 4; j++) {
            int n = bn + tx * 4 + j;
            if (m < M && n < N) C[(size_t)m * N + n] = acc[i][j];
        }
    }
}

// -------- depthwise causal conv (K=4) + SiLU + optional per-head RMSNorm --------
// one block per (b,t,h); 128 threads (one per d)
__global__ void conv_silu_norm(const float* __restrict__ pre, const float* __restrict__ w,
                               float* __restrict__ out, float postscale, int do_norm) {
    int blk = blockIdx.x;              // b*T*H + t*H + h
    int h = blk % Hh;
    int bt = blk / Hh;                 // b*T + t
    int t = bt % Tq;
    int d = threadIdx.x;
    int c = h * Dd + d;

    float acc = 0.f;
#pragma unroll
    for (int j = 0; j < 4; j++) {
        int tt = t - 3 + j;
        if (tt >= 0) acc += pre[(size_t)(bt - t + tt) * HIDN + c] * w[c * 4 + j];
    }
    acc = acc / (1.f + expf(-acc));    // SiLU
    float val = acc;
    if (do_norm) {
        float ss = acc * acc;
#pragma unroll
        for (int off = 16; off > 0; off >>= 1) ss += __shfl_xor_sync(0xffffffffu, ss, off);
        __shared__ float sh[4];
        if ((threadIdx.x & 31) == 0) sh[threadIdx.x >> 5] = ss;
        __syncthreads();
        float tot = sh[0] + sh[1] + sh[2] + sh[3];
        val = acc * rsqrtf(tot * (1.f / 128.f) + 1e-6f) * postscale;
    }
    out[(size_t)bt * HIDN + c] = val;
}

// -------- g = -exp(A_log[h]) * softplus(a + dt_bias) (in place on a) --------
__global__ void g_transform(float* __restrict__ a, const float* __restrict__ dt_bias,
                            const float* __restrict__ A_log) {
    int idx = blockIdx.x * blockDim.x + threadIdx.x;
    if (idx >= BT * HIDN) return;
    int c = idx % HIDN;
    int h = c / Dd;
    float x = a[idx] + dt_bias[c];
    float sp = (x > 0.f) ? (x + log1pf(expf(-x))) : log1pf(expf(x));
    a[idx] = -expf(A_log[h]) * sp;
}

__global__ void sigmoid_inplace(float* __restrict__ p, int n) {
    int idx = blockIdx.x * blockDim.x + threadIdx.x;
    if (idx < n) p[idx] = 1.f / (1.f + expf(-p[idx]));
}

// -------- gated delta-rule scan: one block per (b,h), thread j owns S[:,j] --------
__global__ void __launch_bounds__(128, 1)
scan_kernel(const float* __restrict__ q, const float* __restrict__ k,
            const float* __restrict__ v, const float* __restrict__ g,
            const float* __restrict__ beta, float* __restrict__ out) {
    int b = blockIdx.x >> 3;
    int h = blockIdx.x & 7;
    int j = threadIdx.x;
    __shared__ float ks[Dd], qs[Dd], egs[Dd];
    float S[Dd];
#pragma unroll
    for (int i = 0; i < Dd; i++) S[i] = 0.f;

    for (int t = 0; t < Tq; t++) {
        size_t row = (size_t)(b * Tq + t) * HIDN + h * Dd;
        ks[j]  = k[row + j];
        qs[j]  = q[row + j];
        egs[j] = expf(g[row + j]);
        float vj = v[row + j];
        float bt = beta[(b * Tq + t) * Hh + h];
        __syncthreads();

        float kv0 = 0.f, kv1 = 0.f, kv2 = 0.f, kv3 = 0.f;
#pragma unroll
        for (int i = 0; i < Dd; i += 4) {
            float s0 = S[i    ] * egs[i    ]; S[i    ] = s0; kv0 += ks[i    ] * s0;
            float s1 = S[i + 1] * egs[i + 1]; S[i + 1] = s1; kv1 += ks[i + 1] * s1;
            float s2 = S[i + 2] * egs[i + 2]; S[i + 2] = s2; kv2 += ks[i + 2] * s2;
            float s3 = S[i + 3] * egs[i + 3]; S[i + 3] = s3; kv3 += ks[i + 3] * s3;
        }
        float delta = bt * (vj - (kv0 + kv1 + kv2 + kv3));

        float o0 = 0.f, o1 = 0.f, o2 = 0.f, o3 = 0.f;
#pragma unroll
        for (int i = 0; i < Dd; i += 4) {
            float s0 = S[i    ] + ks[i    ] * delta; S[i    ] = s0; o0 += qs[i    ] * s0;
            float s1 = S[i + 1] + ks[i + 1] * delta; S[i + 1] = s1; o1 += qs[i + 1] * s1;
            float s2 = S[i + 2] + ks[i + 2] * delta; S[i + 2] = s2; o2 += qs[i + 2] * s2;
            float s3 = S[i + 3] + ks[i + 3] * delta; S[i + 3] = s3; o3 += qs[i + 3] * s3;
        }
        out[row + j] = o0 + o1 + o2 + o3;
        __syncthreads();
    }
}

// -------- output RMSNorm * o_norm_w * sigmoid(gate), in place on attn --------
__global__ void out_norm_gate(float* __restrict__ attn, const float* __restrict__ gate,
                              const float* __restrict__ onw) {
    int blk = blockIdx.x;
    int h = blk % Hh;
    int bt = blk / Hh;
    int d = threadIdx.x;
    size_t idx = (size_t)bt * HIDN + h * Dd + d;
    float val = attn[idx];
    float ss = val * val;
#pragma unroll
    for (int off = 16; off > 0; off >>= 1) ss += __shfl_xor_sync(0xffffffffu, ss, off);
    __shared__ float sh[4];
    if ((threadIdx.x & 31) == 0) sh[threadIdx.x >> 5] = ss;
    __syncthreads();
    float tot = sh[0] + sh[1] + sh[2] + sh[3];
    float gt = gate[idx];
    attn[idx] = val * rsqrtf(tot * (1.f / 128.f) + 1e-5f) * onw[d]
              * (1.f / (1.f + expf(-gt)));
}

// ---------------------------------- launch ----------------------------------
extern "C" void kernel_launch(void* const* d_in, const int* in_sizes, int n_in,
                              void* d_out, int out_size) {
    const float* x       = (const float*)d_in[0];
    const float* Wq      = (const float*)d_in[1];
    const float* Wk      = (const float*)d_in[2];
    const float* Wv      = (const float*)d_in[3];
    const float* wq_conv = (const float*)d_in[4];
    const float* wk_conv = (const float*)d_in[5];
    const float* wv_conv = (const float*)d_in[6];
    const float* Wfa     = (const float*)d_in[7];
    const float* Wfb     = (const float*)d_in[8];
    const float* Wb      = (const float*)d_in[9];
    const float* Wga     = (const float*)d_in[10];
    const float* Wgb     = (const float*)d_in[11];
    const float* A_log   = (const float*)d_in[12];
    const float* dt_bias = (const float*)d_in[13];
    const float* onw     = (const float*)d_in[14];
    const float* Wo      = (const float*)d_in[15];
    float* out = (float*)d_out;

    float *qpre, *kpre, *vpre, *qn, *kn, *vn, *fa, *gbuf, *betab, *gab, *gateb, *attn;
    cudaGetSymbolAddress((void**)&qpre, g_qpre);
    cudaGetSymbolAddress((void**)&kpre, g_kpre);
    cudaGetSymbolAddress((void**)&vpre, g_vpre);
    cudaGetSymbolAddress((void**)&qn, g_qn);
    cudaGetSymbolAddress((void**)&kn, g_kn);
    cudaGetSymbolAddress((void**)&vn, g_vn);
    cudaGetSymbolAddress((void**)&fa, g_fa);
    cudaGetSymbolAddress((void**)&gbuf, g_gbuf);
    cudaGetSymbolAddress((void**)&betab, g_betab);
    cudaGetSymbolAddress((void**)&gab, g_gab);
    cudaGetSymbolAddress((void**)&gateb, g_gateb);
    cudaGetSymbolAddress((void**)&attn, g_attn);

    dim3 gBig((HIDN + GBN - 1) / GBN, (BT + GBM - 1) / GBM);   // 16 x 32
    dim3 gNar((Dd + GBN - 1) / GBN, (BT + GBM - 1) / GBM);     //  2 x 32
    dim3 gBeta(1, (BT + GBM - 1) / GBM);                       //  1 x 32

    // projections
    gemm_nt<<<gBig, 256>>>(x, Wq, qpre, BT, HIDN, HIDN);
    gemm_nt<<<gBig, 256>>>(x, Wk, kpre, BT, HIDN, HIDN);
    gemm_nt<<<gBig, 256>>>(x, Wv, vpre, BT, HIDN, HIDN);
    gemm_nt<<<gNar, 256>>>(x, Wfa, fa, BT, Dd, HIDN);
    gemm_nt<<<gNar, 256>>>(x, Wga, gab, BT, Dd, HIDN);
    gemm_nt<<<gBeta, 256>>>(x, Wb, betab, BT, Hh, HIDN);
    gemm_nt<<<gBig, 256>>>(fa, Wfb, gbuf, BT, HIDN, Dd);
    gemm_nt<<<gBig, 256>>>(gab, Wgb, gateb, BT, HIDN, Dd);

    // conv + silu (+ head rmsnorm with q/k scaling)
    conv_silu_norm<<<BT * Hh, 128>>>(qpre, wq_conv, qn, 1.f / 128.f, 1);             // scale^2
    conv_silu_norm<<<BT * Hh, 128>>>(kpre, wk_conv, kn, 0.08838834764831845f, 1);    // scale
    conv_silu_norm<<<BT * Hh, 128>>>(vpre, wv_conv, vn, 1.f, 0);

    // g and beta nonlinearity
    g_transform<<<(BT * HIDN + 255) / 256, 256>>>(gbuf, dt_bias, A_log);
    sigmoid_inplace<<<(BT * Hh + 255) / 256, 256>>>(betab, BT * Hh);

    // recurrence
    scan_kernel<<<Bq * Hh, 128>>>(qn, kn, vn, gbuf, betab, attn);

    // output norm/gate + final projection
    out_norm_gate<<<BT * Hh, 128>>>(attn, gateb, onw);
    gemm_nt<<<gBig, 256>>>(attn, Wo, out, BT, HIDN, HIDN);
}

// round 2
// speedup vs baseline: 1.0005x; 1.0005x over previous
#include <cuda_runtime.h>
#include <math.h>

#define Bq  2
#define Tq  1024
#define Hh  8
#define Dd  128
#define HIDN 1024
#define BT  (Bq*Tq)

// ---------------- scratch (device globals; no allocation allowed) ----------------
__device__ float g_qpre[BT*HIDN];
__device__ float g_kpre[BT*HIDN];
__device__ float g_vpre[BT*HIDN];
__device__ float g_qn[BT*HIDN];
__device__ float g_kn[BT*HIDN];
__device__ float g_vn[BT*HIDN];
__device__ float g_fa[BT*Dd];
__device__ float g_gbuf[BT*HIDN];
__device__ float g_betab[BT*Hh];
__device__ float g_gab[BT*Dd];
__device__ float g_gateb[BT*HIDN];
__device__ float g_attn[BT*HIDN];

// ---------------- generic fp32 GEMM: C[M,N] = A[M,K] * B[N,K]^T ----------------
#define GBM 64
#define GBN 64
#define GBK 16
__global__ void gemm_nt(const float* __restrict__ A, const float* __restrict__ Bm,
                        float* __restrict__ C, int M, int N, int K) {
    __shared__ float As[GBK][GBM + 1];
    __shared__ float Bs[GBK][GBN + 1];
    int tid = threadIdx.x;
    int tx = tid & 15, ty = tid >> 4;
    int bm = blockIdx.y * GBM, bn = blockIdx.x * GBN;
    float acc[4][4];
#pragma unroll
    for (int i = 0; i < 4; i++)
#pragma unroll
        for (int j = 0; j < 4; j++) acc[i][j] = 0.f;

    for (int k0 = 0; k0 < K; k0 += GBK) {
        int col = tid & 15;
#pragma unroll
        for (int r0 = 0; r0 < GBM; r0 += 16) {
            int r = r0 + (tid >> 4);
            // M is always a multiple of 64 here (2048); rows of A always valid
            As[col][r] = A[(size_t)(bm + r) * K + k0 + col];
            Bs[col][r] = (bn + r < N) ? Bm[(size_t)(bn + r) * K + k0 + col] : 0.f;
        }
        __syncthreads();
#pragma unroll
        for (int kk = 0; kk < GBK; kk++) {
            float ra[4], rb[4];
#pragma unroll
            for (int i = 0; i < 4; i++) ra[i] = As[kk][ty * 4 + i];
#pragma unroll
            for (int j = 0; j < 4; j++) rb[j] = Bs[kk][tx * 4 + j];
#pragma unroll
            for (int i = 0; i < 4; i++)
#pragma unroll
                for (int j = 0; j < 4; j++)
                    acc[i][j] += ra[i] * rb[j];
        }
        __syncthreads();
    }
#pragma unroll
    for (int i = 0; i < 4; i++) {
        int m = bm + ty * 4 + i;
#pragma unroll
        for (int j = 0; j < 4; j++) {
            int n = bn + tx * 4 + j;
            if (m < M && n < N) C[(size_t)m * N + n] = acc[i][j];
        }
    }
}

// -------- depthwise causal conv (K=4) + SiLU + optional per-head RMSNorm --------
// one block per (b,t,h); 128 threads (one per d)
__global__ void conv_silu_norm(const float* __restrict__ pre, const float* __restrict__ w,
                               float* __restrict__ out, float postscale, int do_norm) {
    int blk = blockIdx.x;              // b*T*H + t*H + h
    int h = blk % Hh;
    int bt = blk / Hh;                 // b*T + t
    int t = bt % Tq;
    int d = threadIdx.x;
    int c = h * Dd + d;

    float acc = 0.f;
#pragma unroll
    for (int j = 0; j < 4; j++) {
        int tt = t - 3 + j;
        if (tt >= 0) acc += pre[(size_t)(bt - t + tt) * HIDN + c] * w[c * 4 + j];
    }
    acc = acc / (1.f + expf(-acc));    // SiLU
    float val = acc;
    if (do_norm) {
        float ss = acc * acc;
#pragma unroll
        for (int off = 16; off > 0; off >>= 1) ss += __shfl_xor_sync(0xffffffffu, ss, off);
        __shared__ float sh[4];
        if ((threadIdx.x & 31) == 0) sh[threadIdx.x >> 5] = ss;
        __syncthreads();
        float tot = sh[0] + sh[1] + sh[2] + sh[3];
        val = acc * rsqrtf(tot * (1.f / 128.f) + 1e-6f) * postscale;
    }
    out[(size_t)bt * HIDN + c] = val;
}

// -------- g = -exp(A_log[h]) * softplus(a + dt_bias) (in place on a) --------
__global__ void g_transform(float* __restrict__ a, const float* __restrict__ dt_bias,
                            const float* __restrict__ A_log) {
    int idx = blockIdx.x * blockDim.x + threadIdx.x;
    if (idx >= BT * HIDN) return;
    int c = idx % HIDN;
    int h = c / Dd;
    float x = a[idx] + dt_bias[c];
    float sp = (x > 0.f) ? (x + log1pf(expf(-x))) : log1pf(expf(x));
    a[idx] = -expf(A_log[h]) * sp;
}

__global__ void sigmoid_inplace(float* __restrict__ p, int n) {
    int idx = blockIdx.x * blockDim.x + threadIdx.x;
    if (idx < n) p[idx] = 1.f / (1.f + expf(-p[idx]));
}

// -------- gated delta-rule scan: one block per (b,h), thread j owns S[:,j] --------
__global__ void __launch_bounds__(128, 1)
scan_kernel(const float* __restrict__ q, const float* __restrict__ k,
            const float* __restrict__ v, const float* __restrict__ g,
            const float* __restrict__ beta, float* __restrict__ out) {
    int b = blockIdx.x >> 3;
    int h = blockIdx.x & 7;
    int j = threadIdx.x;
    __shared__ float ks[Dd], qs[Dd], egs[Dd];
    float S[Dd];
#pragma unroll
    for (int i = 0; i < Dd; i++) S[i] = 0.f;

    for (int t = 0; t < Tq; t++) {
        size_t row = (size_t)(b * Tq + t) * HIDN + h * Dd;
        ks[j]  = k[row + j];
        qs[j]  = q[row + j];
        egs[j] = expf(g[row + j]);
        float vj = v[row + j];
        float bt = beta[(b * Tq + t) * Hh + h];
        __syncthreads();

        float kv0 = 0.f, kv1 = 0.f, kv2 = 0.f, kv3 = 0.f;
#pragma unroll
        for (int i = 0; i < Dd; i += 4) {
            float s0 = S[i    ] * egs[i    ]; S[i    ] = s0; kv0 += ks[i    ] * s0;
            float s1 = S[i + 1] * egs[i + 1]; S[i + 1] = s1; kv1 += ks[i + 1] * s1;
            float s2 = S[i + 2] * egs[i + 2]; S[i + 2] = s2; kv2 += ks[i + 2] * s2;
            float s3 = S[i + 3] * egs[i + 3]; S[i + 3] = s3; kv3 += ks[i + 3] * s3;
        }
        float delta = bt * (vj - (kv0 + kv1 + kv2 + kv3));

        float o0 = 0.f, o1 = 0.f, o2 = 0.f, o3 = 0.f;
#pragma unroll
        for (int i = 0; i < Dd; i += 4) {
            float s0 = S[i    ] + ks[i    ] * delta; S[i    ] = s0; o0 += qs[i    ] * s0;
            float s1 = S[i + 1] + ks[i + 1] * delta; S[i + 1] = s1; o1 += qs[i + 1] * s1;
            float s2 = S[i + 2] + ks[i + 2] * delta; S[i + 2] = s2; o2 += qs[i + 2] * s2;
            float s3 = S[i + 3] + ks[i + 3] * delta; S[i + 3] = s3; o3 += qs[i + 3] * s3;
        }
        out[row + j] = o0 + o1 + o2 + o3;
        __syncthreads();
    }
}

// -------- output RMSNorm * o_norm_w * sigmoid(gate), in place on attn --------
__global__ void out_norm_gate(float* __restrict__ attn, const float* __restrict__ gate,
                              const float* __restrict__ onw) {
    int blk = blockIdx.x;
    int h = blk % Hh;
    int bt = blk / Hh;
    int d = threadIdx.x;
    size_t idx = (size_t)bt * HIDN + h * Dd + d;
    float val = attn[idx];
    float ss = val * val;
#pragma unroll
    for (int off = 16; off > 0; off >>= 1) ss += __shfl_xor_sync(0xffffffffu, ss, off);
    __shared__ float sh[4];
    if ((threadIdx.x & 31) == 0) sh[threadIdx.x >> 5] = ss;
    __syncthreads();
    float tot = sh[0] + sh[1] + sh[2] + sh[3];
    float gt = gate[idx];
    attn[idx] = val * rsqrtf(tot * (1.f / 128.f) + 1e-5f) * onw[d]
              * (1.f / (1.f + expf(-gt)));
}

// ---------------------------------- launch ----------------------------------
extern "C" void kernel_launch(void* const* d_in, const int* in_sizes, int n_in,
                              void* d_out, int out_size) {
    const float* x       = (const float*)d_in[0];
    const float* Wq      = (const float*)d_in[1];
    const float* Wk      = (const float*)d_in[2];
    const float* Wv      = (const float*)d_in[3];
    const float* wq_conv = (const float*)d_in[4];
    const float* wk_conv = (const float*)d_in[5];
    const float* wv_conv = (const float*)d_in[6];
    const float* Wfa     = (const float*)d_in[7];
    const float* Wfb     = (const float*)d_in[8];
    const float* Wb      = (const float*)d_in[9];
    const float* Wga     = (const float*)d_in[10];
    const float* Wgb     = (const float*)d_in[11];
    const float* A_log   = (const float*)d_in[12];
    const float* dt_bias = (const float*)d_in[13];
    const float* onw     = (const float*)d_in[14];
    const float* Wo      = (const float*)d_in[15];
    float* out = (float*)d_out;

    float *qpre, *kpre, *vpre, *qn, *kn, *vn, *fa, *gbuf, *betab, *gab, *gateb, *attn;
    cudaGetSymbolAddress((void**)&qpre, g_qpre);
    cudaGetSymbolAddress((void**)&kpre, g_kpre);
    cudaGetSymbolAddress((void**)&vpre, g_vpre);
    cudaGetSymbolAddress((void**)&qn, g_qn);
    cudaGetSymbolAddress((void**)&kn, g_kn);
    cudaGetSymbolAddress((void**)&vn, g_vn);
    cudaGetSymbolAddress((void**)&fa, g_fa);
    cudaGetSymbolAddress((void**)&gbuf, g_gbuf);
    cudaGetSymbolAddress((void**)&betab, g_betab);
    cudaGetSymbolAddress((void**)&gab, g_gab);
    cudaGetSymbolAddress((void**)&gateb, g_gateb);
    cudaGetSymbolAddress((void**)&attn, g_attn);

    dim3 gBig((HIDN + GBN - 1) / GBN, (BT + GBM - 1) / GBM);   // 16 x 32
    dim3 gNar((Dd + GBN - 1) / GBN, (BT + GBM - 1) / GBM);     //  2 x 32
    dim3 gBeta(1, (BT + GBM - 1) / GBM);                       //  1 x 32

    // projections
    gemm_nt<<<gBig, 256>>>(x, Wq, qpre, BT, HIDN, HIDN);
    gemm_nt<<<gBig, 256>>>(x, Wk, kpre, BT, HIDN, HIDN);
    gemm_nt<<<gBig, 256>>>(x, Wv, vpre, BT, HIDN, HIDN);
    gemm_nt<<<gNar, 256>>>(x, Wfa, fa, BT, Dd, HIDN);
    gemm_nt<<<gNar, 256>>>(x, Wga, gab, BT, Dd, HIDN);
    gemm_nt<<<gBeta, 256>>>(x, Wb, betab, BT, Hh, HIDN);
    gemm_nt<<<gBig, 256>>>(fa, Wfb, gbuf, BT, HIDN, Dd);
    gemm_nt<<<gBig, 256>>>(gab, Wgb, gateb, BT, HIDN, Dd);

    // conv + silu (+ head rmsnorm with q/k scaling)
    conv_silu_norm<<<BT * Hh, 128>>>(qpre, wq_conv, qn, 1.f / 128.f, 1);             // scale^2
    conv_silu_norm<<<BT * Hh, 128>>>(kpre, wk_conv, kn, 0.08838834764831845f, 1);    // scale
    conv_silu_norm<<<BT * Hh, 128>>>(vpre, wv_conv, vn, 1.f, 0);

    // g and beta nonlinearity
    g_transform<<<(BT * HIDN + 255) / 256, 256>>>(gbuf, dt_bias, A_log);
    sigmoid_inplace<<<(BT * Hh + 255) / 256, 256>>>(betab, BT * Hh);

    // recurrence
    scan_kernel<<<Bq * Hh, 128>>>(qn, kn, vn, gbuf, betab, attn);

    // output norm/gate + final projection
    out_norm_gate<<<BT * Hh, 128>>>(attn, gateb, onw);
    gemm_nt<<<gBig, 256>>>(attn, Wo, out, BT, HIDN, HIDN);
}

// round 3
// speedup vs baseline: 3.6762x; 3.6742x over previous
#include <cuda_runtime.h>
#include <math.h>

#define Bq  2
#define Tq  1024
#define Hh  8
#define Dd  128
#define HIDN 1024
#define BT  (Bq*Tq)

// ---------------- scratch (device globals; no allocation allowed) ----------------
__device__ float g_pre[3ull*BT*HIDN];      // qpre,kpre,vpre
__device__ float g_qkvn[3ull*BT*HIDN];     // qn,kn,vn
__device__ float g_nar[2ull*BT*Dd];        // fa, gab
__device__ float g_narpart[8ull*BT*Dd];    // 2 outputs x 4 K-slices
__device__ float g_lr[2ull*BT*HIDN];       // gbuf (g), gateb
__device__ float g_betab[BT*Hh];
__device__ float g_attn[BT*HIDN];

// ============ 128x128x8 register-blocked GEMM: C = A[M,K] * W[N,K]^T ============
// grid.z selects weight (W0/W1/W2), A += z*sAz, C += z*sCz. All dims multiples of tile.
__global__ void __launch_bounds__(256, 2)
gemm128(const float* __restrict__ A, size_t sAz,
        const float* __restrict__ W0, const float* __restrict__ W1, const float* __restrict__ W2,
        float* __restrict__ C, size_t sCz, int N, int K) {
    const float* W = (blockIdx.z == 0) ? W0 : (blockIdx.z == 1 ? W1 : W2);
    A += sAz * blockIdx.z;
    C += sCz * blockIdx.z;
    __shared__ float As[2][8][128];
    __shared__ float Bs[2][8][128];
    int tid = threadIdx.x;
    int bm = blockIdx.y * 128, bn = blockIdx.x * 128;
    int lrow = tid >> 1, lcol = (tid & 1) * 4;
    const float* Ag = A + (size_t)(bm + lrow) * K + lcol;
    const float* Bg = W + (size_t)(bn + lrow) * K + lcol;
    int tx = tid & 15, ty = tid >> 4;
    float acc[8][8];
#pragma unroll
    for (int i = 0; i < 8; i++)
#pragma unroll
        for (int j = 0; j < 8; j++) acc[i][j] = 0.f;

    int nk = K >> 3;
    float4 a4 = *(const float4*)Ag;
    float4 b4 = *(const float4*)Bg;
    As[0][lcol+0][lrow] = a4.x; As[0][lcol+1][lrow] = a4.y;
    As[0][lcol+2][lrow] = a4.z; As[0][lcol+3][lrow] = a4.w;
    Bs[0][lcol+0][lrow] = b4.x; Bs[0][lcol+1][lrow] = b4.y;
    Bs[0][lcol+2][lrow] = b4.z; Bs[0][lcol+3][lrow] = b4.w;
    __syncthreads();

    for (int kt = 0; kt < nk; kt++) {
        int buf = kt & 1;
        if (kt + 1 < nk) {
            a4 = *(const float4*)(Ag + (size_t)(kt + 1) * 8);
            b4 = *(const float4*)(Bg + (size_t)(kt + 1) * 8);
        }
#pragma unroll
        for (int kk = 0; kk < 8; kk++) {
            float4 x0 = *(const float4*)&As[buf][kk][ty * 4];
            float4 x1 = *(const float4*)&As[buf][kk][64 + ty * 4];
            float4 y0 = *(const float4*)&Bs[buf][kk][tx * 4];
            float4 y1 = *(const float4*)&Bs[buf][kk][64 + tx * 4];
            float av[8] = {x0.x, x0.y, x0.z, x0.w, x1.x, x1.y, x1.z, x1.w};
            float bv[8] = {y0.x, y0.y, y0.z, y0.w, y1.x, y1.y, y1.z, y1.w};
#pragma unroll
            for (int i = 0; i < 8; i++)
#pragma unroll
                for (int j = 0; j < 8; j++)
                    acc[i][j] = fmaf(av[i], bv[j], acc[i][j]);
        }
        if (kt + 1 < nk) {
            int nb = buf ^ 1;
            As[nb][lcol+0][lrow] = a4.x; As[nb][lcol+1][lrow] = a4.y;
            As[nb][lcol+2][lrow] = a4.z; As[nb][lcol+3][lrow] = a4.w;
            Bs[nb][lcol+0][lrow] = b4.x; Bs[nb][lcol+1][lrow] = b4.y;
            Bs[nb][lcol+2][lrow] = b4.z; Bs[nb][lcol+3][lrow] = b4.w;
        }
        __syncthreads();
    }
#pragma unroll
    for (int i = 0; i < 8; i++) {
        int m = bm + ((i < 4) ? (ty * 4 + i) : (64 + ty * 4 + i - 4));
        float4 v0 = make_float4(acc[i][0], acc[i][1], acc[i][2], acc[i][3]);
        float4 v1 = make_float4(acc[i][4], acc[i][5], acc[i][6], acc[i][7]);
        *(float4*)&C[(size_t)m * N + bn + tx * 4] = v0;
        *(float4*)&C[(size_t)m * N + bn + 64 + tx * 4] = v1;
    }
}

// ======== narrow split-K GEMM: N=128, K=1024 split into 4 slices of 256 ========
// grid = (4 slices, 16 m-tiles, 2 outputs); partials to g_narpart[(z*4+s)*BT*128]
__global__ void __launch_bounds__(256, 2)
gemm_narrow_splitk(const float* __restrict__ A,
                   const float* __restrict__ W0, const float* __restrict__ W1,
                   float* __restrict__ part) {
    const float* W = (blockIdx.z == 0) ? W0 : W1;
    int s = blockIdx.x;
    float* C = part + ((size_t)(blockIdx.z * 4 + s)) * BT * Dd;
    __shared__ float As[2][8][128];
    __shared__ float Bs[2][8][128];
    int tid = threadIdx.x;
    int bm = blockIdx.y * 128;
    int k0 = s * 256;
    int lrow = tid >> 1, lcol = (tid & 1) * 4;
    const float* Ag = A + (size_t)(bm + lrow) * 1024 + k0 + lcol;
    const float* Bg = W + (size_t)lrow * 1024 + k0 + lcol;
    int tx = tid & 15, ty = tid >> 4;
    float acc[8][8];
#pragma unroll
    for (int i = 0; i < 8; i++)
#pragma unroll
        for (int j = 0; j < 8; j++) acc[i][j] = 0.f;

    const int nk = 32;
    float4 a4 = *(const float4*)Ag;
    float4 b4 = *(const float4*)Bg;
    As[0][lcol+0][lrow] = a4.x; As[0][lcol+1][lrow] = a4.y;
    As[0][lcol+2][lrow] = a4.z; As[0][lcol+3][lrow] = a4.w;
    Bs[0][lcol+0][lrow] = b4.x; Bs[0][lcol+1][lrow] = b4.y;
    Bs[0][lcol+2][lrow] = b4.z; Bs[0][lcol+3][lrow] = b4.w;
    __syncthreads();

    for (int kt = 0; kt < nk; kt++) {
        int buf = kt & 1;
        if (kt + 1 < nk) {
            a4 = *(const float4*)(Ag + (size_t)(kt + 1) * 8);
            b4 = *(const float4*)(Bg + (size_t)(kt + 1) * 8);
        }
#pragma unroll
        for (int kk = 0; kk < 8; kk++) {
            float4 x0 = *(const float4*)&As[buf][kk][ty * 4];
            float4 x1 = *(const float4*)&As[buf][kk][64 + ty * 4];
            float4 y0 = *(const float4*)&Bs[buf][kk][tx * 4];
            float4 y1 = *(const float4*)&Bs[buf][kk][64 + tx * 4];
            float av[8] = {x0.x, x0.y, x0.z, x0.w, x1.x, x1.y, x1.z, x1.w};
            float bv[8] = {y0.x, y0.y, y0.z, y0.w, y1.x, y1.y, y1.z, y1.w};
#pragma unroll
            for (int i = 0; i < 8; i++)
#pragma unroll
                for (int j = 0; j < 8; j++)
                    acc[i][j] = fmaf(av[i], bv[j], acc[i][j]);
        }
        if (kt + 1 < nk) {
            int nb = buf ^ 1;
            As[nb][lcol+0][lrow] = a4.x; As[nb][lcol+1][lrow] = a4.y;
            As[nb][lcol+2][lrow] = a4.z; As[nb][lcol+3][lrow] = a4.w;
            Bs[nb][lcol+0][lrow] = b4.x; Bs[nb][lcol+1][lrow] = b4.y;
            Bs[nb][lcol+2][lrow] = b4.z; Bs[nb][lcol+3][lrow] = b4.w;
        }
        __syncthreads();
    }
#pragma unroll
    for (int i = 0; i < 8; i++) {
        int m = bm + ((i < 4) ? (ty * 4 + i) : (64 + ty * 4 + i - 4));
        float4 v0 = make_float4(acc[i][0], acc[i][1], acc[i][2], acc[i][3]);
        float4 v1 = make_float4(acc[i][4], acc[i][5], acc[i][6], acc[i][7]);
        *(float4*)&C[(size_t)m * Dd + tx * 4] = v0;
        *(float4*)&C[(size_t)m * Dd + 64 + tx * 4] = v1;
    }
}

__global__ void narrow_reduce(const float* __restrict__ part, float* __restrict__ out) {
    size_t idx = (size_t)blockIdx.x * blockDim.x + threadIdx.x;   // over 2*BT*128
    if (idx >= 2ull * BT * Dd) return;
    size_t z = idx / (BT * Dd);
    size_t i = idx - z * (BT * Dd);
    const float* p = part + z * 4ull * BT * Dd;
    out[idx] = p[i] + p[i + (size_t)BT * Dd] + p[i + 2ull * BT * Dd] + p[i + 3ull * BT * Dd];
}

// ---- beta = sigmoid(x @ Wb^T): one warp per (row, head) ----
__global__ void beta_kernel(const float* __restrict__ x, const float* __restrict__ Wb,
                            float* __restrict__ out) {
    int row = blockIdx.x;
    int h = threadIdx.x >> 5;
    int l = threadIdx.x & 31;
    const float* xr = x + (size_t)row * HIDN;
    const float* wr = Wb + (size_t)h * HIDN;
    float acc = 0.f;
#pragma unroll 8
    for (int i = l; i < HIDN; i += 32) acc = fmaf(xr[i], wr[i], acc);
#pragma unroll
    for (int off = 16; off > 0; off >>= 1) acc += __shfl_xor_sync(0xffffffffu, acc, off);
    if (l == 0) out[row * Hh + h] = 1.f / (1.f + expf(-acc));
}

// -------- depthwise causal conv (K=4) + SiLU + optional per-head RMSNorm --------
__global__ void conv_silu_norm(const float* __restrict__ pre, const float* __restrict__ w,
                               float* __restrict__ out, float postscale, int do_norm) {
    int blk = blockIdx.x;              // bt*H + h
    int h = blk % Hh;
    int bt = blk / Hh;
    int t = bt % Tq;
    int d = threadIdx.x;
    int c = h * Dd + d;

    float acc = 0.f;
#pragma unroll
    for (int j = 0; j < 4; j++) {
        int tt = t - 3 + j;
        if (tt >= 0) acc += pre[(size_t)(bt - t + tt) * HIDN + c] * w[c * 4 + j];
    }
    acc = acc / (1.f + expf(-acc));
    float val = acc;
    if (do_norm) {
        float ss = acc * acc;
#pragma unroll
        for (int off = 16; off > 0; off >>= 1) ss += __shfl_xor_sync(0xffffffffu, ss, off);
        __shared__ float sh[4];
        if ((threadIdx.x & 31) == 0) sh[threadIdx.x >> 5] = ss;
        __syncthreads();
        float tot = sh[0] + sh[1] + sh[2] + sh[3];
        val = acc * rsqrtf(tot * (1.f / 128.f) + 1e-6f) * postscale;
    }
    out[(size_t)bt * HIDN + c] = val;
}

// -------- g = -exp(A_log[h]) * softplus(a + dt_bias) --------
__global__ void g_transform(float* __restrict__ a, const float* __restrict__ dt_bias,
                            const float* __restrict__ A_log) {
    int idx = blockIdx.x * blockDim.x + threadIdx.x;
    if (idx >= BT * HIDN) return;
    int c = idx % HIDN;
    int h = c / Dd;
    float x = a[idx] + dt_bias[c];
    float sp = (x > 0.f) ? (x + log1pf(expf(-x))) : log1pf(expf(x));
    a[idx] = -expf(A_log[h]) * sp;
}

// -------- gated delta-rule scan: 16 lanes per Dv column, 8 Dk rows per lane --------
// grid (16 bh, 8 col-groups), 256 threads. col = grp*16 + (tid>>4), r = tid&15,
// Dk rows i = r + 16*ii (ii<8). One __syncthreads per step (double-buffered smem).
__global__ void __launch_bounds__(256, 1)
scan_kernel(const float* __restrict__ q, const float* __restrict__ k,
            const float* __restrict__ v, const float* __restrict__ g,
            const float* __restrict__ beta, float* __restrict__ out) {
    int bh = blockIdx.x;
    int b = bh >> 3, h = bh & 7;
    int tid = threadIdx.x;
    int col = blockIdx.y * 16 + (tid >> 4);
    int r = tid & 15;
    __shared__ float ks[2][Dd], qs[2][Dd], egs[2][Dd], vs[2][Dd];
    __shared__ float bb[2];
    float S[8];
#pragma unroll
    for (int i = 0; i < 8; i++) S[i] = 0.f;
    size_t rowbase = (size_t)b * Tq * HIDN + h * Dd;

    for (int t = 0; t < Tq; t++) {
        int buf = t & 1;
        size_t row = rowbase + (size_t)t * HIDN;
        if (tid < 128) {
            ks[buf][tid] = k[row + tid];
            qs[buf][tid] = q[row + tid];
        } else {
            int d = tid - 128;
            egs[buf][d] = __expf(g[row + d]);
            vs[buf][d] = v[row + d];
        }
        if (tid == 0) bb[buf] = beta[(b * Tq + t) * Hh + h];
        __syncthreads();

        float kr[8];
        float kv = 0.f;
#pragma unroll
        for (int ii = 0; ii < 8; ii++) {
            int i = r + 16 * ii;
            float kk = ks[buf][i];
            kr[ii] = kk;
            float s = S[ii] * egs[buf][i];
            S[ii] = s;
            kv = fmaf(kk, s, kv);
        }
        kv += __shfl_xor_sync(0xffffffffu, kv, 1);
        kv += __shfl_xor_sync(0xffffffffu, kv, 2);
        kv += __shfl_xor_sync(0xffffffffu, kv, 4);
        kv += __shfl_xor_sync(0xffffffffu, kv, 8);
        float delta = bb[buf] * (vs[buf][col] - kv);

        float o = 0.f;
#pragma unroll
        for (int ii = 0; ii < 8; ii++) {
            int i = r + 16 * ii;
            float s = fmaf(kr[ii], delta, S[ii]);
            S[ii] = s;
            o = fmaf(qs[buf][i], s, o);
        }
        o += __shfl_xor_sync(0xffffffffu, o, 1);
        o += __shfl_xor_sync(0xffffffffu, o, 2);
        o += __shfl_xor_sync(0xffffffffu, o, 4);
        o += __shfl_xor_sync(0xffffffffu, o, 8);
        if (r == 0) out[row + col] = o;
    }
}

// -------- output RMSNorm * o_norm_w * sigmoid(gate) --------
__global__ void out_norm_gate(float* __restrict__ attn, const float* __restrict__ gate,
                              const float* __restrict__ onw) {
    int blk = blockIdx.x;
    int h = blk % Hh;
    int bt = blk / Hh;
    int d = threadIdx.x;
    size_t idx = (size_t)bt * HIDN + h * Dd + d;
    float val = attn[idx];
    float ss = val * val;
#pragma unroll
    for (int off = 16; off > 0; off >>= 1) ss += __shfl_xor_sync(0xffffffffu, ss, off);
    __shared__ float sh[4];
    if ((threadIdx.x & 31) == 0) sh[threadIdx.x >> 5] = ss;
    __syncthreads();
    float tot = sh[0] + sh[1] + sh[2] + sh[3];
    float gt = gate[idx];
    attn[idx] = val * rsqrtf(tot * (1.f / 128.f) + 1e-5f) * onw[d]
              * (1.f / (1.f + expf(-gt)));
}

// ---------------------------------- launch ----------------------------------
extern "C" void kernel_launch(void* const* d_in, const int* in_sizes, int n_in,
                              void* d_out, int out_size) {
    const float* x       = (const float*)d_in[0];
    const float* Wq      = (const float*)d_in[1];
    const float* Wk      = (const float*)d_in[2];
    const float* Wv      = (const float*)d_in[3];
    const float* wq_conv = (const float*)d_in[4];
    const float* wk_conv = (const float*)d_in[5];
    const float* wv_conv = (const float*)d_in[6];
    const float* Wfa     = (const float*)d_in[7];
    const float* Wfb     = (const float*)d_in[8];
    const float* Wb      = (const float*)d_in[9];
    const float* Wga     = (const float*)d_in[10];
    const float* Wgb     = (const float*)d_in[11];
    const float* A_log   = (const float*)d_in[12];
    const float* dt_bias = (const float*)d_in[13];
    const float* onw     = (const float*)d_in[14];
    const float* Wo      = (const float*)d_in[15];
    float* out = (float*)d_out;

    float *pre, *qkvn, *nar, *narpart, *lr, *betab, *attn;
    cudaGetSymbolAddress((void**)&pre, g_pre);
    cudaGetSymbolAddress((void**)&qkvn, g_qkvn);
    cudaGetSymbolAddress((void**)&nar, g_nar);
    cudaGetSymbolAddress((void**)&narpart, g_narpart);
    cudaGetSymbolAddress((void**)&lr, g_lr);
    cudaGetSymbolAddress((void**)&betab, g_betab);
    cudaGetSymbolAddress((void**)&attn, g_attn);

    const size_t S1 = (size_t)BT * HIDN;
    const size_t SD = (size_t)BT * Dd;

    // QKV projections (fused via grid.z)
    gemm128<<<dim3(8, 16, 3), 256>>>(x, 0, Wq, Wk, Wv, pre, S1, HIDN, HIDN);
    // narrow low-rank "a" projections, split-K + reduce
    gemm_narrow_splitk<<<dim3(4, 16, 2), 256>>>(x, Wfa, Wga, narpart);
    narrow_reduce<<<(unsigned)((2 * SD + 255) / 256), 256>>>(narpart, nar);
    // low-rank expansions: gbuf = fa @ Wfb^T, gateb = gab @ Wgb^T (fused via grid.z)
    gemm128<<<dim3(8, 16, 2), 256>>>(nar, SD, Wfb, Wgb, Wgb, lr, S1, HIDN, Dd);
    // beta
    beta_kernel<<<BT, 256>>>(x, Wb, betab);

    // conv + silu (+ head rmsnorm; q gets scale^2 = 1/128, k gets scale = 1/sqrt(128))
    conv_silu_norm<<<BT * Hh, 128>>>(pre,          wq_conv, qkvn,          1.f / 128.f, 1);
    conv_silu_norm<<<BT * Hh, 128>>>(pre + S1,     wk_conv, qkvn + S1,     0.08838834764831845f, 1);
    conv_silu_norm<<<BT * Hh, 128>>>(pre + 2 * S1, wv_conv, qkvn + 2 * S1, 1.f, 0);

    // g nonlinearity (in place on lr[0])
    g_transform<<<(BT * HIDN + 255) / 256, 256>>>(lr, dt_bias, A_log);

    // recurrence
    scan_kernel<<<dim3(16, 8), 256>>>(qkvn, qkvn + S1, qkvn + 2 * S1, lr, betab, attn);

    // output norm/gate + final projection
    out_norm_gate<<<BT * Hh, 128>>>(attn, lr + S1, onw);
    gemm128<<<dim3(8, 16, 1), 256>>>(attn, 0, Wo, Wo, Wo, out, 0, HIDN, HIDN);
}

// round 5
// speedup vs baseline: 4.9655x; 1.3507x over previous
#include <cuda_runtime.h>
#include <math.h>
#include <stdint.h>

#define Bq  2
#define Tq  1024
#define Hh  8
#define Dd  128
#define HIDN 1024
#define BT  (Bq*Tq)

#if defined(__CUDA_ARCH_FEAT_SM103_ALL) || defined(__CUDA_ARCH_FEAT_SM100_ALL)
#define HAS_TCGEN05 1
#else
#define HAS_TCGEN05 0
#endif

// ---------------- scratch (device globals; no allocation allowed) ----------------
__device__ float g_pre[3ull*BT*HIDN];      // qpre,kpre,vpre
__device__ float g_qkvn[3ull*BT*HIDN];     // qn,kn,vn
__device__ float g_nar[2ull*BT*Dd];        // fa, gab
__device__ float g_lr[2ull*BT*HIDN];       // gbuf (g), gateb
__device__ float g_betab[BT*Hh];
__device__ float g_attn[BT*HIDN];

// ============================ PTX helpers ============================
__device__ __forceinline__ uint32_t smem_u32(const void* p) {
    uint32_t a;
    asm("{ .reg .u64 t; cvta.to.shared.u64 t, %1; cvt.u32.u64 %0, t; }" : "=r"(a) : "l"(p));
    return a;
}

#if HAS_TCGEN05
#define MBARRIER_INIT(addr, cnt) \
    asm volatile("mbarrier.init.shared.b64 [%0], %1;" :: "r"(addr), "r"(cnt) : "memory")

#define MBARRIER_WAIT_PARITY(mbar_smem_addr, phase_parity) do { \
    uint32_t _mbar = (uint32_t)(mbar_smem_addr); \
    uint32_t _parity = (uint32_t)(phase_parity); \
    uint32_t _done; \
    asm volatile( \
        "{\n\t.reg .pred p;\n\t" \
        "mbarrier.try_wait.parity.acquire.cta.shared::cta.b64 p, [%1], %2;\n\t" \
        "selp.b32 %0, 1, 0, p;\n\t}" \
        : "=r"(_done) : "r"(_mbar), "r"(_parity) : "memory"); \
    if (!_done) { \
        asm volatile( \
            "{\n\t.reg .pred P1;\n\t" \
            "WAIT_LOOP_%=:\n\t" \
            "mbarrier.try_wait.parity.acquire.cta.shared::cta.b64 P1, [%0], %1, 0x989680;\n\t" \
            "@P1 bra.uni WAIT_DONE_%=;\n\t" \
            "bra.uni WAIT_LOOP_%=;\n\t" \
            "WAIT_DONE_%=:\n\t}" \
            :: "r"(_mbar), "r"(_parity) : "memory"); \
    } \
} while(0)

#define TCGEN05_ALLOC(smem_result_addr, nCols) \
    asm volatile("tcgen05.alloc.cta_group::1.sync.aligned.shared::cta.b32 [%0], %1;" \
        :: "r"((uint32_t)(smem_result_addr)), "r"((uint32_t)(nCols)) : "memory")
#define TCGEN05_DEALLOC(tmem_addr, nCols) \
    asm volatile("tcgen05.dealloc.cta_group::1.sync.aligned.b32 %0, %1;" \
        :: "r"(tmem_addr), "r"((uint32_t)(nCols)))
#define TCGEN05_RELINQUISH() \
    asm volatile("tcgen05.relinquish_alloc_permit.cta_group::1.sync.aligned;")
#define TCGEN05_COMMIT(mbar_smem_addr) \
    asm volatile("tcgen05.commit.cta_group::1.mbarrier::arrive::one.shared::cluster.b64 [%0];" \
        :: "r"((uint32_t)(mbar_smem_addr)) : "memory")
#define TCGEN05_FENCE_AFTER() \
    asm volatile("tcgen05.fence::after_thread_sync;" ::: "memory")
#define TCGEN05_FENCE_BEFORE() \
    asm volatile("tcgen05.fence::before_thread_sync;" ::: "memory")
#define TCGEN05_WAIT_LD() \
    asm volatile("tcgen05.wait::ld.sync.aligned;" ::: "memory")
#define FENCE_ASYNC_SHARED() \
    asm volatile("fence.proxy.async.shared::cta;" ::: "memory")

#define TCGEN05_MMA_TF32(d_tmem, a_desc, b_desc, idesc, enable_d) do { \
    uint32_t _en = (enable_d) ? 1u : 0u; \
    uint32_t _zero = 0u; \
    asm volatile( \
        "{\n\t.reg .pred p;\n\tsetp.ne.u32 p, %6, 0;\n\t" \
        "tcgen05.mma.cta_group::1.kind::tf32 [%0], %1, %2, %3, {%4, %4, %4, %4}, p;\n\t}" \
        :: "r"(d_tmem), "l"(a_desc), "l"(b_desc), "r"(idesc), \
           "r"(_zero), "r"(_zero), "r"(_en) : "memory"); \
} while(0)

#define TCGEN05_LD_32X32B_X32(r, tmem_addr) \
    asm volatile( \
        "tcgen05.ld.sync.aligned.32x32b.x32.b32 " \
        "{%0, %1, %2, %3, %4, %5, %6, %7, " \
        " %8, %9, %10, %11, %12, %13, %14, %15, " \
        " %16, %17, %18, %19, %20, %21, %22, %23, " \
        " %24, %25, %26, %27, %28, %29, %30, %31}, [%32];" \
        : "=r"((r)[0]),  "=r"((r)[1]),  "=r"((r)[2]),  "=r"((r)[3]), \
          "=r"((r)[4]),  "=r"((r)[5]),  "=r"((r)[6]),  "=r"((r)[7]), \
          "=r"((r)[8]),  "=r"((r)[9]),  "=r"((r)[10]), "=r"((r)[11]), \
          "=r"((r)[12]), "=r"((r)[13]), "=r"((r)[14]), "=r"((r)[15]), \
          "=r"((r)[16]), "=r"((r)[17]), "=r"((r)[18]), "=r"((r)[19]), \
          "=r"((r)[20]), "=r"((r)[21]), "=r"((r)[22]), "=r"((r)[23]), \
          "=r"((r)[24]), "=r"((r)[25]), "=r"((r)[26]), "=r"((r)[27]), \
          "=r"((r)[28]), "=r"((r)[29]), "=r"((r)[30]), "=r"((r)[31]) \
        : "r"(tmem_addr))
#endif  // HAS_TCGEN05

static constexpr uint64_t SMEM_DESC_BASE_SW128 =
    (uint64_t(2)  << 61) | (uint64_t(1) << 46) | (uint64_t(64) << 32) | (uint64_t(1) << 16);
#define MAKE_SMEM_DESC(base_addr) \
    (SMEM_DESC_BASE_SW128 | ((uint64_t)((base_addr) >> 4) & 0x3FFF))

// idesc: dtype=F32(1<<4), atype=TF32(2<<7), btype=TF32(2<<10), N=128(16<<17), M=128(8<<24)
#define IDESC_TF32 0x08200910u

// ============ GEMM: C[M,:] tile = A[M,K] * W[N,K]^T, 128x128 tiles ============
// grid.z selects weight; A += z*sAz, C += z*sCz. K multiple of 32, tile N=128.
// sm_103a path: tcgen05 tf32 SS, double-buffered 128x32 fp32 SW128 chunks.
// plain sm_103 path: SIMT register-blocked fallback (insurance; not expected to run).
#define CHUNK_BYTES 16384   // 128 rows * 32 fp32 * 4B
__global__ void __launch_bounds__(128, 3)
gemm_tc(const float* __restrict__ A, size_t sAz,
        const float* __restrict__ W0, const float* __restrict__ W1, const float* __restrict__ W2,
        float* __restrict__ C, size_t sCz, int N, int K) {
    extern __shared__ char dynraw[];
    __shared__ uint32_t tptr_slot;
    __shared__ uint64_t mbar[2];

    const float* W = (blockIdx.z == 0) ? W0 : (blockIdx.z == 1 ? W1 : W2);
    A += sAz * blockIdx.z;
    C += sCz * blockIdx.z;

    int tid = threadIdx.x;
    int bm = blockIdx.y * 128, bn = blockIdx.x * 128;

    uint32_t dynaddr = smem_u32(dynraw);
    uint32_t base = (dynaddr + 1023u) & ~1023u;
    char* buf_ptr = dynraw + (base - dynaddr);

#if HAS_TCGEN05
    uint32_t mb0 = smem_u32(&mbar[0]);
    uint32_t mb1 = smem_u32(&mbar[1]);

    if (tid < 32) {
        TCGEN05_ALLOC(smem_u32(&tptr_slot), 128);
        TCGEN05_RELINQUISH();
    }
    if (tid == 0) { MBARRIER_INIT(mb0, 1); MBARRIER_INIT(mb1, 1); }
    __syncthreads();
    uint32_t tmem = tptr_slot;

    const float* Ag = A + (size_t)bm * K;
    const float* Bg = W + (size_t)bn * K;
    int nk = K >> 5;
    int ph0 = 0, ph1 = 0;

    for (int kt = 0; kt < nk; kt++) {
        int buf = kt & 1;
        if (kt >= 2) {
            if (buf == 0) { MBARRIER_WAIT_PARITY(mb0, ph0); ph0 ^= 1; }
            else          { MBARRIER_WAIT_PARITY(mb1, ph1); ph1 ^= 1; }
        }
        char* bufA = buf_ptr + buf * (2 * CHUNK_BYTES);
        char* bufB = bufA + CHUNK_BYTES;
        const float* Ak = Ag + kt * 32;
        const float* Bk = Bg + kt * 32;
#pragma unroll
        for (int u = 0; u < 8; u++) {
            int id = u * 128 + tid;
            int r = id >> 3, s = id & 7;
            uint32_t swoff = (uint32_t)(r * 128 + ((s ^ (r & 7)) * 16));
            float4 va = *(const float4*)(Ak + (size_t)r * K + s * 4);
            float4 vb = *(const float4*)(Bk + (size_t)r * K + s * 4);
            uint4 ua, ub;
            asm("cvt.rna.tf32.f32 %0, %1;" : "=r"(ua.x) : "f"(va.x));
            asm("cvt.rna.tf32.f32 %0, %1;" : "=r"(ua.y) : "f"(va.y));
            asm("cvt.rna.tf32.f32 %0, %1;" : "=r"(ua.z) : "f"(va.z));
            asm("cvt.rna.tf32.f32 %0, %1;" : "=r"(ua.w) : "f"(va.w));
            asm("cvt.rna.tf32.f32 %0, %1;" : "=r"(ub.x) : "f"(vb.x));
            asm("cvt.rna.tf32.f32 %0, %1;" : "=r"(ub.y) : "f"(vb.y));
            asm("cvt.rna.tf32.f32 %0, %1;" : "=r"(ub.z) : "f"(vb.z));
            asm("cvt.rna.tf32.f32 %0, %1;" : "=r"(ub.w) : "f"(vb.w));
            *(uint4*)(bufA + swoff) = ua;
            *(uint4*)(bufB + swoff) = ub;
        }
        FENCE_ASYNC_SHARED();
        __syncthreads();
        if (tid == 0) {
            uint32_t aaddr = base + buf * (2 * CHUNK_BYTES);
            uint64_t ad = MAKE_SMEM_DESC(aaddr);
            uint64_t bd = MAKE_SMEM_DESC(aaddr + CHUNK_BYTES);
#pragma unroll
            for (int s = 0; s < 4; s++)
                TCGEN05_MMA_TF32(tmem, ad + s * 2, bd + s * 2, IDESC_TF32, (kt > 0) || (s > 0));
            TCGEN05_COMMIT((buf == 0) ? mb0 : mb1);
        }
    }
    if (((nk - 1) & 1) == 0) { MBARRIER_WAIT_PARITY(mb0, ph0); }
    else                     { MBARRIER_WAIT_PARITY(mb1, ph1); }
    TCGEN05_FENCE_AFTER();

    int wid = tid >> 5, lid = tid & 31;
    int m = bm + wid * 32 + lid;
#pragma unroll
    for (int nb = 0; nb < 4; nb++) {
        uint32_t r[32];
        TCGEN05_LD_32X32B_X32(r, tmem + nb * 32);
        TCGEN05_WAIT_LD();
        float4* dst = (float4*)&C[(size_t)m * N + bn + nb * 32];
#pragma unroll
        for (int c = 0; c < 8; c++)
            dst[c] = make_float4(__uint_as_float(r[4*c]), __uint_as_float(r[4*c+1]),
                                 __uint_as_float(r[4*c+2]), __uint_as_float(r[4*c+3]));
    }
    TCGEN05_FENCE_BEFORE();
    __syncthreads();
    if (tid < 32) TCGEN05_DEALLOC(tmem, 128);
#else
    // ---------------- SIMT fallback (plain sm_103 target) ----------------
    (void)tptr_slot; (void)mbar;
    float* As = (float*)buf_ptr;          // [8][128] col-major-ish: As[kk][row]
    float* Bs = As + 8 * 128;             // [8][128]
    int tx = tid & 15, ty = tid >> 4;     // tx: 16 col-groups, ty: 8 row-groups
    float acc[16][8];
#pragma unroll
    for (int i = 0; i < 16; i++)
#pragma unroll
        for (int j = 0; j < 8; j++) acc[i][j] = 0.f;

    int nk8 = K >> 3;
    for (int kt = 0; kt < nk8; kt++) {
        __syncthreads();
#pragma unroll
        for (int f = 0; f < 2; f++) {
            int fi = f * 128 + tid;       // 256 float4 per matrix chunk
            int r = fi >> 1, cg = (fi & 1) * 4;
            float4 va = *(const float4*)(A + (size_t)(bm + r) * K + kt * 8 + cg);
            float4 vb = *(const float4*)(W + (size_t)(bn + r) * K + kt * 8 + cg);
            As[(cg + 0) * 128 + r] = va.x; As[(cg + 1) * 128 + r] = va.y;
            As[(cg + 2) * 128 + r] = va.z; As[(cg + 3) * 128 + r] = va.w;
            Bs[(cg + 0) * 128 + r] = vb.x; Bs[(cg + 1) * 128 + r] = vb.y;
            Bs[(cg + 2) * 128 + r] = vb.z; Bs[(cg + 3) * 128 + r] = vb.w;
        }
        __syncthreads();
#pragma unroll
        for (int kk = 0; kk < 8; kk++) {
            float av[16], bv[8];
#pragma unroll
            for (int g = 0; g < 4; g++) {
                float4 t = *(const float4*)&As[kk * 128 + g * 32 + ty * 4];
                av[g * 4 + 0] = t.x; av[g * 4 + 1] = t.y; av[g * 4 + 2] = t.z; av[g * 4 + 3] = t.w;
            }
            float4 b0 = *(const float4*)&Bs[kk * 128 + tx * 4];
            float4 b1 = *(const float4*)&Bs[kk * 128 + 64 + tx * 4];
            bv[0] = b0.x; bv[1] = b0.y; bv[2] = b0.z; bv[3] = b0.w;
            bv[4] = b1.x; bv[5] = b1.y; bv[6] = b1.z; bv[7] = b1.w;
#pragma unroll
            for (int i = 0; i < 16; i++)
#pragma unroll
                for (int j = 0; j < 8; j++)
                    acc[i][j] = fmaf(av[i], bv[j], acc[i][j]);
        }
    }
#pragma unroll
    for (int i = 0; i < 16; i++) {
        int m = bm + (i >> 2) * 32 + ty * 4 + (i & 3);
        *(float4*)&C[(size_t)m * N + bn + tx * 4] =
            make_float4(acc[i][0], acc[i][1], acc[i][2], acc[i][3]);
        *(float4*)&C[(size_t)m * N + bn + 64 + tx * 4] =
            make_float4(acc[i][4], acc[i][5], acc[i][6], acc[i][7]);
    }
#endif
}

// ---- beta = sigmoid(x @ Wb^T): one warp per (row, head) ----
__global__ void beta_kernel(const float* __restrict__ x, const float* __restrict__ Wb,
                            float* __restrict__ out) {
    int row = blockIdx.x;
    int h = threadIdx.x >> 5;
    int l = threadIdx.x & 31;
    const float* xr = x + (size_t)row * HIDN;
    const float* wr = Wb + (size_t)h * HIDN;
    float acc = 0.f;
#pragma unroll 8
    for (int i = l; i < HIDN; i += 32) acc = fmaf(xr[i], wr[i], acc);
#pragma unroll
    for (int off = 16; off > 0; off >>= 1) acc += __shfl_xor_sync(0xffffffffu, acc, off);
    if (l == 0) out[row * Hh + h] = 1.f / (1.f + expf(-acc));
}

// -------- depthwise causal conv (K=4) + SiLU + optional per-head RMSNorm --------
// grid (BT*Hh, 3): blockIdx.y = which of q/k/v
__global__ void conv_silu_norm(const float* __restrict__ pre_base, const float* __restrict__ wq,
                               const float* __restrict__ wk, const float* __restrict__ wv,
                               float* __restrict__ out_base) {
    int which = blockIdx.y;
    const float* w = (which == 0) ? wq : (which == 1 ? wk : wv);
    const float* pre = pre_base + (size_t)which * BT * HIDN;
    float* out = out_base + (size_t)which * BT * HIDN;
    float postscale = (which == 0) ? (1.f / 128.f) : (which == 1 ? 0.08838834764831845f : 1.f);
    int do_norm = (which < 2);

    int blk = blockIdx.x;
    int h = blk % Hh;
    int bt = blk / Hh;
    int t = bt % Tq;
    int d = threadIdx.x;
    int c = h * Dd + d;

    float acc = 0.f;
#pragma unroll
    for (int j = 0; j < 4; j++) {
        int tt = t - 3 + j;
        if (tt >= 0) acc += pre[(size_t)(bt - t + tt) * HIDN + c] * w[c * 4 + j];
    }
    acc = acc / (1.f + expf(-acc));
    float val = acc;
    if (do_norm) {
        float ss = acc * acc;
#pragma unroll
        for (int off = 16; off > 0; off >>= 1) ss += __shfl_xor_sync(0xffffffffu, ss, off);
        __shared__ float sh[4];
        if ((threadIdx.x & 31) == 0) sh[threadIdx.x >> 5] = ss;
        __syncthreads();
        float tot = sh[0] + sh[1] + sh[2] + sh[3];
        val = acc * rsqrtf(tot * (1.f / 128.f) + 1e-6f) * postscale;
    }
    out[(size_t)bt * HIDN + c] = val;
}

// -------- g = -exp(A_log[h]) * softplus(a + dt_bias) --------
__global__ void g_transform(float* __restrict__ a, const float* __restrict__ dt_bias,
                            const float* __restrict__ A_log) {
    int idx = blockIdx.x * blockDim.x + threadIdx.x;
    if (idx >= BT * HIDN) return;
    int c = idx % HIDN;
    int h = c / Dd;
    float x = a[idx] + dt_bias[c];
    float sp = (x > 0.f) ? (x + log1pf(expf(-x))) : log1pf(expf(x));
    a[idx] = -expf(A_log[h]) * sp;
}

// -------- gated delta-rule scan: 16 lanes per Dv column, 8 Dk rows per lane --------
__global__ void __launch_bounds__(256, 1)
scan_kernel(const float* __restrict__ q, const float* __restrict__ k,
            const float* __restrict__ v, const float* __restrict__ g,
            const float* __restrict__ beta, float* __restrict__ out) {
    int bh = blockIdx.x;
    int b = bh >> 3, h = bh & 7;
    int tid = threadIdx.x;
    int col = blockIdx.y * 16 + (tid >> 4);
    int r = tid & 15;
    __shared__ float ks[2][Dd], qs[2][Dd], egs[2][Dd], vs[2][Dd];
    __shared__ float bb[2];
    float S[8];
#pragma unroll
    for (int i = 0; i < 8; i++) S[i] = 0.f;
    size_t rowbase = (size_t)b * Tq * HIDN + h * Dd;

    for (int t = 0; t < Tq; t++) {
        int buf = t & 1;
        size_t row = rowbase + (size_t)t * HIDN;
        if (tid < 128) {
            ks[buf][tid] = k[row + tid];
            qs[buf][tid] = q[row + tid];
        } else {
            int d = tid - 128;
            egs[buf][d] = __expf(g[row + d]);
            vs[buf][d] = v[row + d];
        }
        if (tid == 0) bb[buf] = beta[(b * Tq + t) * Hh + h];
        __syncthreads();

        float kr[8];
        float kv = 0.f;
#pragma unroll
        for (int ii = 0; ii < 8; ii++) {
            int i = r + 16 * ii;
            float kk = ks[buf][i];
            kr[ii] = kk;
            float s = S[ii] * egs[buf][i];
            S[ii] = s;
            kv = fmaf(kk, s, kv);
        }
        kv += __shfl_xor_sync(0xffffffffu, kv, 1);
        kv += __shfl_xor_sync(0xffffffffu, kv, 2);
        kv += __shfl_xor_sync(0xffffffffu, kv, 4);
        kv += __shfl_xor_sync(0xffffffffu, kv, 8);
        float delta = bb[buf] * (vs[buf][col] - kv);

        float o = 0.f;
#pragma unroll
        for (int ii = 0; ii < 8; ii++) {
            int i = r + 16 * ii;
            float s = fmaf(kr[ii], delta, S[ii]);
            S[ii] = s;
            o = fmaf(qs[buf][i], s, o);
        }
        o += __shfl_xor_sync(0xffffffffu, o, 1);
        o += __shfl_xor_sync(0xffffffffu, o, 2);
        o += __shfl_xor_sync(0xffffffffu, o, 4);
        o += __shfl_xor_sync(0xffffffffu, o, 8);
        if (r == 0) out[row + col] = o;
    }
}

// -------- output RMSNorm * o_norm_w * sigmoid(gate) --------
__global__ void out_norm_gate(float* __restrict__ attn, const float* __restrict__ gate,
                              const float* __restrict__ onw) {
    int blk = blockIdx.x;
    int h = blk % Hh;
    int bt = blk / Hh;
    int d = threadIdx.x;
    size_t idx = (size_t)bt * HIDN + h * Dd + d;
    float val = attn[idx];
    float ss = val * val;
#pragma unroll
    for (int off = 16; off > 0; off >>= 1) ss += __shfl_xor_sync(0xffffffffu, ss, off);
    __shared__ float sh[4];
    if ((threadIdx.x & 31) == 0) sh[threadIdx.x >> 5] = ss;
    __syncthreads();
    float tot = sh[0] + sh[1] + sh[2] + sh[3];
    float gt = gate[idx];
    attn[idx] = val * rsqrtf(tot * (1.f / 128.f) + 1e-5f) * onw[d]
              * (1.f / (1.f + expf(-gt)));
}

// ---------------------------------- launch ----------------------------------
extern "C" void kernel_launch(void* const* d_in, const int* in_sizes, int n_in,
                              void* d_out, int out_size) {
    const float* x       = (const float*)d_in[0];
    const float* Wq      = (const float*)d_in[1];
    const float* Wk      = (const float*)d_in[2];
    const float* Wv      = (const float*)d_in[3];
    const float* wq_conv = (const float*)d_in[4];
    const float* wk_conv = (const float*)d_in[5];
    const float* wv_conv = (const float*)d_in[6];
    const float* Wfa     = (const float*)d_in[7];
    const float* Wfb     = (const float*)d_in[8];
    const float* Wb      = (const float*)d_in[9];
    const float* Wga     = (const float*)d_in[10];
    const float* Wgb     = (const float*)d_in[11];
    const float* A_log   = (const float*)d_in[12];
    const float* dt_bias = (const float*)d_in[13];
    const float* onw     = (const float*)d_in[14];
    const float* Wo      = (const float*)d_in[15];
    float* out = (float*)d_out;

    float *pre, *qkvn, *nar, *lr, *betab, *attn;
    cudaGetSymbolAddress((void**)&pre, g_pre);
    cudaGetSymbolAddress((void**)&qkvn, g_qkvn);
    cudaGetSymbolAddress((void**)&nar, g_nar);
    cudaGetSymbolAddress((void**)&lr, g_lr);
    cudaGetSymbolAddress((void**)&betab, g_betab);
    cudaGetSymbolAddress((void**)&attn, g_attn);

    const size_t S1 = (size_t)BT * HIDN;
    const size_t SD = (size_t)BT * Dd;
    const int SMEM_GEMM = 4 * CHUNK_BYTES + 1024;   // 66560
    cudaFuncSetAttribute(gemm_tc, cudaFuncAttributeMaxDynamicSharedMemorySize, SMEM_GEMM);

    // QKV projections (fused via grid.z)
    gemm_tc<<<dim3(8, 16, 3), 128, SMEM_GEMM>>>(x, 0, Wq, Wk, Wv, pre, S1, HIDN, HIDN);
    // narrow low-rank "a" projections: fa = x@Wfa^T, gab = x@Wga^T (N=128 -> 1 n-tile)
    gemm_tc<<<dim3(1, 16, 2), 128, SMEM_GEMM>>>(x, 0, Wfa, Wga, Wga, nar, SD, Dd, HIDN);
    // low-rank expansions: gbuf = fa @ Wfb^T, gateb = gab @ Wgb^T
    gemm_tc<<<dim3(8, 16, 2), 128, SMEM_GEMM>>>(nar, SD, Wfb, Wgb, Wgb, lr, S1, HIDN, Dd);
    // beta
    beta_kernel<<<BT, 256>>>(x, Wb, betab);

    // conv + silu (+ head rmsnorm; q: scale^2 = 1/128, k: scale = 1/sqrt(128)) — one launch
    conv_silu_norm<<<dim3(BT * Hh, 3), 128>>>(pre, wq_conv, wk_conv, wv_conv, qkvn);

    // g nonlinearity (in place on lr[0])
    g_transform<<<(BT * HIDN + 255) / 256, 256>>>(lr, dt_bias, A_log);

    // recurrence
    scan_kernel<<<dim3(16, 8), 256>>>(qkvn, qkvn + S1, qkvn + 2 * S1, lr, betab, attn);

    // output norm/gate + final projection
    out_norm_gate<<<BT * Hh, 128>>>(attn, lr + S1, onw);
    gemm_tc<<<dim3(8, 16, 1), 128, SMEM_GEMM>>>(attn, 0, Wo, Wo, Wo, out, 0, HIDN, HIDN);
}

// round 6
// speedup vs baseline: 5.4338x; 1.0943x over previous
#include <cuda_runtime.h>
#include <math.h>
#include <stdint.h>

#define Bq  2
#define Tq  1024
#define Hh  8
#define Dd  128
#define HIDN 1024
#define BT  (Bq*Tq)

#if defined(__CUDA_ARCH_FEAT_SM103_ALL) || defined(__CUDA_ARCH_FEAT_SM100_ALL)
#define HAS_TCGEN05 1
#else
#define HAS_TCGEN05 0
#endif

// ---------------- scratch (device globals; no allocation allowed) ----------------
__device__ float g_pre[3ull*BT*HIDN];      // qpre,kpre,vpre
__device__ float g_qkvn[3ull*BT*HIDN];     // qn,kn,vn
__device__ float g_nar[2ull*BT*Dd];        // fa, gab
__device__ float g_lr[2ull*BT*HIDN];       // eg (exp of g), gateb
__device__ float g_betab[BT*Hh];
__device__ float g_attn[BT*HIDN];

// ============================ PTX helpers ============================
__device__ __forceinline__ uint32_t smem_u32(const void* p) {
    uint32_t a;
    asm("{ .reg .u64 t; cvta.to.shared.u64 t, %1; cvt.u32.u64 %0, t; }" : "=r"(a) : "l"(p));
    return a;
}

#if HAS_TCGEN05
#define MBARRIER_INIT(addr, cnt) \
    asm volatile("mbarrier.init.shared.b64 [%0], %1;" :: "r"(addr), "r"(cnt) : "memory")

#define MBARRIER_WAIT_PARITY(mbar_smem_addr, phase_parity) do { \
    uint32_t _mbar = (uint32_t)(mbar_smem_addr); \
    uint32_t _parity = (uint32_t)(phase_parity); \
    uint32_t _done; \
    asm volatile( \
        "{\n\t.reg .pred p;\n\t" \
        "mbarrier.try_wait.parity.acquire.cta.shared::cta.b64 p, [%1], %2;\n\t" \
        "selp.b32 %0, 1, 0, p;\n\t}" \
        : "=r"(_done) : "r"(_mbar), "r"(_parity) : "memory"); \
    if (!_done) { \
        asm volatile( \
            "{\n\t.reg .pred P1;\n\t" \
            "WAIT_LOOP_%=:\n\t" \
            "mbarrier.try_wait.parity.acquire.cta.shared::cta.b64 P1, [%0], %1, 0x989680;\n\t" \
            "@P1 bra.uni WAIT_DONE_%=;\n\t" \
            "bra.uni WAIT_LOOP_%=;\n\t" \
            "WAIT_DONE_%=:\n\t}" \
            :: "r"(_mbar), "r"(_parity) : "memory"); \
    } \
} while(0)

#define TCGEN05_ALLOC(smem_result_addr, nCols) \
    asm volatile("tcgen05.alloc.cta_group::1.sync.aligned.shared::cta.b32 [%0], %1;" \
        :: "r"((uint32_t)(smem_result_addr)), "r"((uint32_t)(nCols)) : "memory")
#define TCGEN05_DEALLOC(tmem_addr, nCols) \
    asm volatile("tcgen05.dealloc.cta_group::1.sync.aligned.b32 %0, %1;" \
        :: "r"(tmem_addr), "r"((uint32_t)(nCols)))
#define TCGEN05_RELINQUISH() \
    asm volatile("tcgen05.relinquish_alloc_permit.cta_group::1.sync.aligned;")
#define TCGEN05_COMMIT(mbar_smem_addr) \
    asm volatile("tcgen05.commit.cta_group::1.mbarrier::arrive::one.shared::cluster.b64 [%0];" \
        :: "r"((uint32_t)(mbar_smem_addr)) : "memory")
#define TCGEN05_FENCE_AFTER() \
    asm volatile("tcgen05.fence::after_thread_sync;" ::: "memory")
#define TCGEN05_FENCE_BEFORE() \
    asm volatile("tcgen05.fence::before_thread_sync;" ::: "memory")
#define TCGEN05_WAIT_LD() \
    asm volatile("tcgen05.wait::ld.sync.aligned;" ::: "memory")
#define FENCE_ASYNC_SHARED() \
    asm volatile("fence.proxy.async.shared::cta;" ::: "memory")

#define TCGEN05_MMA_TF32(d_tmem, a_desc, b_desc, idesc, enable_d) do { \
    uint32_t _en = (enable_d) ? 1u : 0u; \
    uint32_t _zero = 0u; \
    asm volatile( \
        "{\n\t.reg .pred p;\n\tsetp.ne.u32 p, %6, 0;\n\t" \
        "tcgen05.mma.cta_group::1.kind::tf32 [%0], %1, %2, %3, {%4, %4, %4, %4}, p;\n\t}" \
        :: "r"(d_tmem), "l"(a_desc), "l"(b_desc), "r"(idesc), \
           "r"(_zero), "r"(_zero), "r"(_en) : "memory"); \
} while(0)

#define TCGEN05_LD_32X32B_X32(r, tmem_addr) \
    asm volatile( \
        "tcgen05.ld.sync.aligned.32x32b.x32.b32 " \
        "{%0, %1, %2, %3, %4, %5, %6, %7, " \
        " %8, %9, %10, %11, %12, %13, %14, %15, " \
        " %16, %17, %18, %19, %20, %21, %22, %23, " \
        " %24, %25, %26, %27, %28, %29, %30, %31}, [%32];" \
        : "=r"((r)[0]),  "=r"((r)[1]),  "=r"((r)[2]),  "=r"((r)[3]), \
          "=r"((r)[4]),  "=r"((r)[5]),  "=r"((r)[6]),  "=r"((r)[7]), \
          "=r"((r)[8]),  "=r"((r)[9]),  "=r"((r)[10]), "=r"((r)[11]), \
          "=r"((r)[12]), "=r"((r)[13]), "=r"((r)[14]), "=r"((r)[15]), \
          "=r"((r)[16]), "=r"((r)[17]), "=r"((r)[18]), "=r"((r)[19]), \
          "=r"((r)[20]), "=r"((r)[21]), "=r"((r)[22]), "=r"((r)[23]), \
          "=r"((r)[24]), "=r"((r)[25]), "=r"((r)[26]), "=r"((r)[27]), \
          "=r"((r)[28]), "=r"((r)[29]), "=r"((r)[30]), "=r"((r)[31]) \
        : "r"(tmem_addr))
#endif  // HAS_TCGEN05

static constexpr uint64_t SMEM_DESC_BASE_SW128 =
    (uint64_t(2)  << 61) | (uint64_t(1) << 46) | (uint64_t(64) << 32) | (uint64_t(1) << 16);
#define MAKE_SMEM_DESC(base_addr) \
    (SMEM_DESC_BASE_SW128 | ((uint64_t)((base_addr) >> 4) & 0x3FFF))

// idesc: dtype=F32(1<<4), atype=TF32(2<<7), btype=TF32(2<<10), N=128(16<<17), M=128(8<<24)
#define IDESC_TF32 0x08200910u

// ============ GEMM: C[M,:] tile = A[M,K] * W[N,K]^T, 128x128 tiles ============
// grid.z selects weight; A += z*sAz, C += z*sCz. K multiple of 32, tile N=128.
// sm_103a path: tcgen05 tf32 SS, double-buffered 128x32 fp32 SW128 chunks, 256 threads.
#define CHUNK_BYTES 16384   // 128 rows * 32 fp32 * 4B
__global__ void __launch_bounds__(256, 3)
gemm_tc(const float* __restrict__ A, size_t sAz,
        const float* __restrict__ W0, const float* __restrict__ W1, const float* __restrict__ W2,
        float* __restrict__ C, size_t sCz, int N, int K) {
    extern __shared__ char dynraw[];
    __shared__ uint32_t tptr_slot;
    __shared__ uint64_t mbar[2];

    const float* W = (blockIdx.z == 0) ? W0 : (blockIdx.z == 1 ? W1 : W2);
    A += sAz * blockIdx.z;
    C += sCz * blockIdx.z;

    int tid = threadIdx.x;
    int bm = blockIdx.y * 128, bn = blockIdx.x * 128;

    uint32_t dynaddr = smem_u32(dynraw);
    uint32_t base = (dynaddr + 1023u) & ~1023u;
    char* buf_ptr = dynraw + (base - dynaddr);

#if HAS_TCGEN05
    uint32_t mb0 = smem_u32(&mbar[0]);
    uint32_t mb1 = smem_u32(&mbar[1]);

    if (tid < 32) {
        TCGEN05_ALLOC(smem_u32(&tptr_slot), 128);
        TCGEN05_RELINQUISH();
    }
    if (tid == 0) { MBARRIER_INIT(mb0, 1); MBARRIER_INIT(mb1, 1); }
    __syncthreads();
    uint32_t tmem = tptr_slot;

    const float* Ag = A + (size_t)bm * K;
    const float* Bg = W + (size_t)bn * K;
    int nk = K >> 5;
    int ph0 = 0, ph1 = 0;

    for (int kt = 0; kt < nk; kt++) {
        int buf = kt & 1;
        if (kt >= 2) {
            if (buf == 0) { MBARRIER_WAIT_PARITY(mb0, ph0); ph0 ^= 1; }
            else          { MBARRIER_WAIT_PARITY(mb1, ph1); ph1 ^= 1; }
        }
        char* bufA = buf_ptr + buf * (2 * CHUNK_BYTES);
        char* bufB = bufA + CHUNK_BYTES;
        const float* Ak = Ag + kt * 32;
        const float* Bk = Bg + kt * 32;
#pragma unroll
        for (int u = 0; u < 4; u++) {
            int id = u * 256 + tid;
            int r = id >> 3, s = id & 7;
            uint32_t swoff = (uint32_t)(r * 128 + ((s ^ (r & 7)) * 16));
            float4 va = *(const float4*)(Ak + (size_t)r * K + s * 4);
            float4 vb = *(const float4*)(Bk + (size_t)r * K + s * 4);
            uint4 ua, ub;
            asm("cvt.rna.tf32.f32 %0, %1;" : "=r"(ua.x) : "f"(va.x));
            asm("cvt.rna.tf32.f32 %0, %1;" : "=r"(ua.y) : "f"(va.y));
            asm("cvt.rna.tf32.f32 %0, %1;" : "=r"(ua.z) : "f"(va.z));
            asm("cvt.rna.tf32.f32 %0, %1;" : "=r"(ua.w) : "f"(va.w));
            asm("cvt.rna.tf32.f32 %0, %1;" : "=r"(ub.x) : "f"(vb.x));
            asm("cvt.rna.tf32.f32 %0, %1;" : "=r"(ub.y) : "f"(vb.y));
            asm("cvt.rna.tf32.f32 %0, %1;" : "=r"(ub.z) : "f"(vb.z));
            asm("cvt.rna.tf32.f32 %0, %1;" : "=r"(ub.w) : "f"(vb.w));
            *(uint4*)(bufA + swoff) = ua;
            *(uint4*)(bufB + swoff) = ub;
        }
        FENCE_ASYNC_SHARED();
        __syncthreads();
        if (tid == 0) {
            uint32_t aaddr = base + buf * (2 * CHUNK_BYTES);
            uint64_t ad = MAKE_SMEM_DESC(aaddr);
            uint64_t bd = MAKE_SMEM_DESC(aaddr + CHUNK_BYTES);
#pragma unroll
            for (int s = 0; s < 4; s++)
                TCGEN05_MMA_TF32(tmem, ad + s * 2, bd + s * 2, IDESC_TF32, (kt > 0) || (s > 0));
            TCGEN05_COMMIT((buf == 0) ? mb0 : mb1);
        }
    }
    if (((nk - 1) & 1) == 0) { MBARRIER_WAIT_PARITY(mb0, ph0); }
    else                     { MBARRIER_WAIT_PARITY(mb1, ph1); }
    TCGEN05_FENCE_AFTER();

    // 8-warp epilogue: warps 0-3 cols 0-63, warps 4-7 cols 64-127 (two warpgroups)
    int wid = tid >> 5, lane = tid & 31;
    int m = bm + (wid & 3) * 32 + lane;
    int nbbase = (wid >> 2) * 2;
#pragma unroll
    for (int it = 0; it < 2; it++) {
        int nb = nbbase + it;
        uint32_t r[32];
        TCGEN05_LD_32X32B_X32(r, tmem + nb * 32);
        TCGEN05_WAIT_LD();
        float4* dst = (float4*)&C[(size_t)m * N + bn + nb * 32];
#pragma unroll
        for (int c = 0; c < 8; c++)
            dst[c] = make_float4(__uint_as_float(r[4*c]), __uint_as_float(r[4*c+1]),
                                 __uint_as_float(r[4*c+2]), __uint_as_float(r[4*c+3]));
    }
    TCGEN05_FENCE_BEFORE();
    __syncthreads();
    if (tid < 32) TCGEN05_DEALLOC(tmem, 128);
#else
    // ---------------- SIMT fallback (plain sm_103 target; not expected to run) ----------------
    (void)tptr_slot; (void)mbar;
    float* As = (float*)buf_ptr;          // [8][128]
    float* Bs = As + 8 * 128;             // [8][128]
    int tx = tid & 15, ty = tid >> 4;     // 16 x 16
    float acc[8][8];
#pragma unroll
    for (int i = 0; i < 8; i++)
#pragma unroll
        for (int j = 0; j < 8; j++) acc[i][j] = 0.f;

    int nk8 = K >> 3;
    for (int kt = 0; kt < nk8; kt++) {
        __syncthreads();
        {
            int r = tid >> 1, cg = (tid & 1) * 4;
            float4 va = *(const float4*)(A + (size_t)(bm + r) * K + kt * 8 + cg);
            float4 vb = *(const float4*)(W + (size_t)(bn + r) * K + kt * 8 + cg);
            As[(cg + 0) * 128 + r] = va.x; As[(cg + 1) * 128 + r] = va.y;
            As[(cg + 2) * 128 + r] = va.z; As[(cg + 3) * 128 + r] = va.w;
            Bs[(cg + 0) * 128 + r] = vb.x; Bs[(cg + 1) * 128 + r] = vb.y;
            Bs[(cg + 2) * 128 + r] = vb.z; Bs[(cg + 3) * 128 + r] = vb.w;
        }
        __syncthreads();
#pragma unroll
        for (int kk = 0; kk < 8; kk++) {
            float av[8], bv[8];
#pragma unroll
            for (int i = 0; i < 8; i++) av[i] = As[kk * 128 + ty * 8 + i];
#pragma unroll
            for (int j = 0; j < 8; j++) bv[j] = Bs[kk * 128 + tx * 8 + j];
#pragma unroll
            for (int i = 0; i < 8; i++)
#pragma unroll
                for (int j = 0; j < 8; j++)
                    acc[i][j] = fmaf(av[i], bv[j], acc[i][j]);
        }
    }
#pragma unroll
    for (int i = 0; i < 8; i++) {
        int m = bm + ty * 8 + i;
#pragma unroll
        for (int j = 0; j < 8; j++)
            C[(size_t)m * N + bn + tx * 8 + j] = acc[i][j];
    }
#endif
}

// ---- beta = sigmoid(x @ Wb^T): one warp per (row, head) ----
__global__ void beta_kernel(const float* __restrict__ x, const float* __restrict__ Wb,
                            float* __restrict__ out) {
    int row = blockIdx.x;
    int h = threadIdx.x >> 5;
    int l = threadIdx.x & 31;
    const float* xr = x + (size_t)row * HIDN;
    const float* wr = Wb + (size_t)h * HIDN;
    float acc = 0.f;
#pragma unroll 8
    for (int i = l; i < HIDN; i += 32) acc = fmaf(xr[i], wr[i], acc);
#pragma unroll
    for (int off = 16; off > 0; off >>= 1) acc += __shfl_xor_sync(0xffffffffu, acc, off);
    if (l == 0) out[row * Hh + h] = 1.f / (1.f + expf(-acc));
}

// -------- depthwise causal conv (K=4) + SiLU + optional per-head RMSNorm --------
__global__ void conv_silu_norm(const float* __restrict__ pre_base, const float* __restrict__ wq,
                               const float* __restrict__ wk, const float* __restrict__ wv,
                               float* __restrict__ out_base) {
    int which = blockIdx.y;
    const float* w = (which == 0) ? wq : (which == 1 ? wk : wv);
    const float* pre = pre_base + (size_t)which * BT * HIDN;
    float* out = out_base + (size_t)which * BT * HIDN;
    float postscale = (which == 0) ? (1.f / 128.f) : (which == 1 ? 0.08838834764831845f : 1.f);
    int do_norm = (which < 2);

    int blk = blockIdx.x;
    int h = blk % Hh;
    int bt = blk / Hh;
    int t = bt % Tq;
    int d = threadIdx.x;
    int c = h * Dd + d;

    float acc = 0.f;
#pragma unroll
    for (int j = 0; j < 4; j++) {
        int tt = t - 3 + j;
        if (tt >= 0) acc += pre[(size_t)(bt - t + tt) * HIDN + c] * w[c * 4 + j];
    }
    acc = acc / (1.f + expf(-acc));
    float val = acc;
    if (do_norm) {
        float ss = acc * acc;
#pragma unroll
        for (int off = 16; off > 0; off >>= 1) ss += __shfl_xor_sync(0xffffffffu, ss, off);
        __shared__ float sh[4];
        if ((threadIdx.x & 31) == 0) sh[threadIdx.x >> 5] = ss;
        __syncthreads();
        float tot = sh[0] + sh[1] + sh[2] + sh[3];
        val = acc * rsqrtf(tot * (1.f / 128.f) + 1e-6f) * postscale;
    }
    out[(size_t)bt * HIDN + c] = val;
}

// -------- eg = exp(-exp(A_log[h]) * softplus(a + dt_bias))  (exp FOLDED in) --------
__global__ void g_transform(float* __restrict__ a, const float* __restrict__ dt_bias,
                            const float* __restrict__ A_log) {
    int idx = blockIdx.x * blockDim.x + threadIdx.x;
    if (idx >= BT * HIDN) return;
    int c = idx % HIDN;
    int h = c / Dd;
    float x = a[idx] + dt_bias[c];
    float sp = (x > 0.f) ? (x + log1pf(expf(-x))) : log1pf(expf(x));
    a[idx] = expf(-expf(A_log[h]) * sp);
}

// ------- gated delta-rule scan: register-only, warp-synchronous, prefetched -------
// grid (16 bh, 8 colgroups), 128 threads. Warp owns 4 cols (8 lanes/col);
// lane: sub = lane>>3 (col), r = lane&7 -> S rows r*16..r*16+15 in registers.
__global__ void __launch_bounds__(128, 1)
scan_kernel(const float* __restrict__ q, const float* __restrict__ k,
            const float* __restrict__ v, const float* __restrict__ eg,
            const float* __restrict__ beta, float* __restrict__ out) {
    int bh = blockIdx.x;
    int b = bh >> 3, h = bh & 7;
    int warp = threadIdx.x >> 5, lane = threadIdx.x & 31;
    int sub = lane >> 3;                    // col within warp (0..3)
    int r = lane & 7;                       // row-group (0..7)
    int col = blockIdx.y * 16 + warp * 4 + sub;
    int rbase = r * 16;
    size_t rowbase = (size_t)b * Tq * HIDN + h * Dd;

    float S[16];
#pragma unroll
    for (int i = 0; i < 16; i++) S[i] = 0.f;

    float4 kc[4], qc[4], ec[4];
    float vc, bc;
    {
        size_t row = rowbase;
#pragma unroll
        for (int ii = 0; ii < 4; ii++) {
            kc[ii] = *(const float4*)(k  + row + rbase + 4 * ii);
            qc[ii] = *(const float4*)(q  + row + rbase + 4 * ii);
            ec[ii] = *(const float4*)(eg + row + rbase + 4 * ii);
        }
        vc = v[row + col];
        bc = beta[(b * Tq) * Hh + h];
    }

    for (int t = 0; t < Tq; t++) {
        size_t row = rowbase + (size_t)t * HIDN;
        float4 kn[4], qn[4], en[4];
        float vn_ = 0.f, bn_ = 0.f;
        if (t + 1 < Tq) {
            size_t rown = row + HIDN;
#pragma unroll
            for (int ii = 0; ii < 4; ii++) {
                kn[ii] = *(const float4*)(k  + rown + rbase + 4 * ii);
                qn[ii] = *(const float4*)(q  + rown + rbase + 4 * ii);
                en[ii] = *(const float4*)(eg + rown + rbase + 4 * ii);
            }
            vn_ = v[rown + col];
            bn_ = beta[(b * Tq + t + 1) * Hh + h];
        }

        // decay + read: kv = sum_i k_i * (S_i * eg_i)
        float kv0 = 0.f, kv1 = 0.f, kv2 = 0.f, kv3 = 0.f;
#pragma unroll
        for (int ii = 0; ii < 4; ii++) {
            float s0 = S[4*ii+0] * ec[ii].x; S[4*ii+0] = s0; kv0 = fmaf(kc[ii].x, s0, kv0);
            float s1 = S[4*ii+1] * ec[ii].y; S[4*ii+1] = s1; kv1 = fmaf(kc[ii].y, s1, kv1);
            float s2 = S[4*ii+2] * ec[ii].z; S[4*ii+2] = s2; kv2 = fmaf(kc[ii].z, s2, kv2);
            float s3 = S[4*ii+3] * ec[ii].w; S[4*ii+3] = s3; kv3 = fmaf(kc[ii].w, s3, kv3);
        }
        float kv = (kv0 + kv1) + (kv2 + kv3);
        kv += __shfl_xor_sync(0xffffffffu, kv, 1);
        kv += __shfl_xor_sync(0xffffffffu, kv, 2);
        kv += __shfl_xor_sync(0xffffffffu, kv, 4);
        float delta = bc * (vc - kv);

        // write + output: S += k*delta; o = sum_i q_i * S_i
        float o0 = 0.f, o1 = 0.f, o2 = 0.f, o3 = 0.f;
#pragma unroll
        for (int ii = 0; ii < 4; ii++) {
            float s0 = fmaf(kc[ii].x, delta, S[4*ii+0]); S[4*ii+0] = s0; o0 = fmaf(qc[ii].x, s0, o0);
            float s1 = fmaf(kc[ii].y, delta, S[4*ii+1]); S[4*ii+1] = s1; o1 = fmaf(qc[ii].y, s1, o1);
            float s2 = fmaf(kc[ii].z, delta, S[4*ii+2]); S[4*ii+2] = s2; o2 = fmaf(qc[ii].z, s2, o2);
            float s3 = fmaf(kc[ii].w, delta, S[4*ii+3]); S[4*ii+3] = s3; o3 = fmaf(qc[ii].w, s3, o3);
        }
        float o = (o0 + o1) + (o2 + o3);
        o += __shfl_xor_sync(0xffffffffu, o, 1);
        o += __shfl_xor_sync(0xffffffffu, o, 2);
        o += __shfl_xor_sync(0xffffffffu, o, 4);
        if (r == 0) out[row + col] = o;

#pragma unroll
        for (int ii = 0; ii < 4; ii++) { kc[ii] = kn[ii]; qc[ii] = qn[ii]; ec[ii] = en[ii]; }
        vc = vn_; bc = bn_;
    }
}

// -------- output RMSNorm * o_norm_w * sigmoid(gate) --------
__global__ void out_norm_gate(float* __restrict__ attn, const float* __restrict__ gate,
                              const float* __restrict__ onw) {
    int blk = blockIdx.x;
    int h = blk % Hh;
    int bt = blk / Hh;
    int d = threadIdx.x;
    size_t idx = (size_t)bt * HIDN + h * Dd + d;
    float val = attn[idx];
    float ss = val * val;
#pragma unroll
    for (int off = 16; off > 0; off >>= 1) ss += __shfl_xor_sync(0xffffffffu, ss, off);
    __shared__ float sh[4];
    if ((threadIdx.x & 31) == 0) sh[threadIdx.x >> 5] = ss;
    __syncthreads();
    float tot = sh[0] + sh[1] + sh[2] + sh[3];
    float gt = gate[idx];
    attn[idx] = val * rsqrtf(tot * (1.f / 128.f) + 1e-5f) * onw[d]
              * (1.f / (1.f + expf(-gt)));
}

// ---------------------------------- launch ----------------------------------
extern "C" void kernel_launch(void* const* d_in, const int* in_sizes, int n_in,
                              void* d_out, int out_size) {
    const float* x       = (const float*)d_in[0];
    const float* Wq      = (const float*)d_in[1];
    const float* Wk      = (const float*)d_in[2];
    const float* Wv      = (const float*)d_in[3];
    const float* wq_conv = (const float*)d_in[4];
    const float* wk_conv = (const float*)d_in[5];
    const float* wv_conv = (const float*)d_in[6];
    const float* Wfa     = (const float*)d_in[7];
    const float* Wfb     = (const float*)d_in[8];
    const float* Wb      = (const float*)d_in[9];
    const float* Wga     = (const float*)d_in[10];
    const float* Wgb     = (const float*)d_in[11];
    const float* A_log   = (const float*)d_in[12];
    const float* dt_bias = (const float*)d_in[13];
    const float* onw     = (const float*)d_in[14];
    const float* Wo      = (const float*)d_in[15];
    float* out = (float*)d_out;

    float *pre, *qkvn, *nar, *lr, *betab, *attn;
    cudaGetSymbolAddress((void**)&pre, g_pre);
    cudaGetSymbolAddress((void**)&qkvn, g_qkvn);
    cudaGetSymbolAddress((void**)&nar, g_nar);
    cudaGetSymbolAddress((void**)&lr, g_lr);
    cudaGetSymbolAddress((void**)&betab, g_betab);
    cudaGetSymbolAddress((void**)&attn, g_attn);

    const size_t S1 = (size_t)BT * HIDN;
    const size_t SD = (size_t)BT * Dd;
    const int SMEM_GEMM = 4 * CHUNK_BYTES + 1024;   // 66560
    cudaFuncSetAttribute(gemm_tc, cudaFuncAttributeMaxDynamicSharedMemorySize, SMEM_GEMM);

    // QKV projections (fused via grid.z)
    gemm_tc<<<dim3(8, 16, 3), 256, SMEM_GEMM>>>(x, 0, Wq, Wk, Wv, pre, S1, HIDN, HIDN);
    // narrow low-rank "a" projections: fa = x@Wfa^T, gab = x@Wga^T (N=128 -> 1 n-tile)
    gemm_tc<<<dim3(1, 16, 2), 256, SMEM_GEMM>>>(x, 0, Wfa, Wga, Wga, nar, SD, Dd, HIDN);
    // low-rank expansions: gbuf = fa @ Wfb^T, gateb = gab @ Wgb^T
    gemm_tc<<<dim3(8, 16, 2), 256, SMEM_GEMM>>>(nar, SD, Wfb, Wgb, Wgb, lr, S1, HIDN, Dd);
    // beta
    beta_kernel<<<BT, 256>>>(x, Wb, betab);

    // conv + silu (+ head rmsnorm; q: scale^2 = 1/128, k: scale = 1/sqrt(128))
    conv_silu_norm<<<dim3(BT * Hh, 3), 128>>>(pre, wq_conv, wk_conv, wv_conv, qkvn);

    // eg = exp(g) (in place on lr[0]; exp folded so scan has no MUFU)
    g_transform<<<(BT * HIDN + 255) / 256, 256>>>(lr, dt_bias, A_log);

    // recurrence (register-only warp-synchronous scan)
    scan_kernel<<<dim3(16, 8), 128>>>(qkvn, qkvn + S1, qkvn + 2 * S1, lr, betab, attn);

    // output norm/gate + final projection
    out_norm_gate<<<BT * Hh, 128>>>(attn, lr + S1, onw);
    gemm_tc<<<dim3(8, 16, 1), 256, SMEM_GEMM>>>(attn, 0, Wo, Wo, Wo, out, 0, HIDN, HIDN);
}

// round 9
// speedup vs baseline: 6.6053x; 1.2156x over previous
#include <cuda_runtime.h>
#include <math.h>
#include <stdint.h>

#define Bq  2
#define Tq  1024
#define Hh  8
#define Dd  128
#define HIDN 1024
#define BT  (Bq*Tq)

#if defined(__CUDA_ARCH_FEAT_SM103_ALL) || defined(__CUDA_ARCH_FEAT_SM100_ALL)
#define HAS_TCGEN05 1
#else
#define HAS_TCGEN05 0
#endif

// ---------------- scratch (device globals; no allocation allowed) ----------------
__device__ float g_pre[3ull*BT*HIDN];      // qpre,kpre,vpre (fp32)
__device__ float g_qkvn[3ull*BT*HIDN];     // qn,kn,vn (fp32)
__device__ float g_nar[2ull*BT*Dd];        // fa, gab (tf32-rounded by epilogue)
__device__ float g_lr[2ull*BT*HIDN];       // eg (exp of g), gateb (fp32)
__device__ float g_betab[BT*Hh];
__device__ float g_attn[BT*HIDN];          // tf32-rounded by out_norm_gate
__device__ float g_xtf[(size_t)BT*HIDN];   // tf32(x)
__device__ float g_wtf[4ull*1048576 + 4ull*131072];  // tf32 weights packed

// packed weight offsets (floats)
#define OWQ  0ull
#define OWK  1048576ull
#define OWV  2097152ull
#define OWO  3145728ull
#define OWFA 4194304ull
#define OWGA 4325376ull
#define OWFB 4456448ull
#define OWGB 4587520ull

// ============================ PTX helpers ============================
__device__ __forceinline__ uint32_t smem_u32(const void* p) {
    uint32_t a;
    asm("{ .reg .u64 t; cvta.to.shared.u64 t, %1; cvt.u32.u64 %0, t; }" : "=r"(a) : "l"(p));
    return a;
}
__device__ __forceinline__ float tf32r(float v) {
    uint32_t u;
    asm("cvt.rna.tf32.f32 %0, %1;" : "=r"(u) : "f"(v));
    return __uint_as_float(u);
}
__device__ __forceinline__ void cp16(uint32_t saddr, const void* gaddr) {
    asm volatile("cp.async.cg.shared.global [%0], [%1], 16;" :: "r"(saddr), "l"(gaddr) : "memory");
}
#define CP_COMMIT()  asm volatile("cp.async.commit_group;" ::: "memory")
#define CP_WAIT_1()  asm volatile("cp.async.wait_group 1;" ::: "memory")
#define CP_WAIT_0()  asm volatile("cp.async.wait_group 0;" ::: "memory")

#if HAS_TCGEN05
#define MBARRIER_INIT(addr, cnt) \
    asm volatile("mbarrier.init.shared.b64 [%0], %1;" :: "r"(addr), "r"(cnt) : "memory")

#define MBARRIER_WAIT_PARITY(mbar_smem_addr, phase_parity) do { \
    uint32_t _mbar = (uint32_t)(mbar_smem_addr); \
    uint32_t _parity = (uint32_t)(phase_parity); \
    uint32_t _done; \
    asm volatile( \
        "{\n\t.reg .pred p;\n\t" \
        "mbarrier.try_wait.parity.acquire.cta.shared::cta.b64 p, [%1], %2;\n\t" \
        "selp.b32 %0, 1, 0, p;\n\t}" \
        : "=r"(_done) : "r"(_mbar), "r"(_parity) : "memory"); \
    if (!_done) { \
        asm volatile( \
            "{\n\t.reg .pred P1;\n\t" \
            "WAIT_LOOP_%=:\n\t" \
            "mbarrier.try_wait.parity.acquire.cta.shared::cta.b64 P1, [%0], %1, 0x989680;\n\t" \
            "@P1 bra.uni WAIT_DONE_%=;\n\t" \
            "bra.uni WAIT_LOOP_%=;\n\t" \
            "WAIT_DONE_%=:\n\t}" \
            :: "r"(_mbar), "r"(_parity) : "memory"); \
    } \
} while(0)

#define TCGEN05_ALLOC(smem_result_addr, nCols) \
    asm volatile("tcgen05.alloc.cta_group::1.sync.aligned.shared::cta.b32 [%0], %1;" \
        :: "r"((uint32_t)(smem_result_addr)), "r"((uint32_t)(nCols)) : "memory")
#define TCGEN05_DEALLOC(tmem_addr, nCols) \
    asm volatile("tcgen05.dealloc.cta_group::1.sync.aligned.b32 %0, %1;" \
        :: "r"(tmem_addr), "r"((uint32_t)(nCols)))
#define TCGEN05_RELINQUISH() \
    asm volatile("tcgen05.relinquish_alloc_permit.cta_group::1.sync.aligned;")
#define TCGEN05_COMMIT(mbar_smem_addr) \
    asm volatile("tcgen05.commit.cta_group::1.mbarrier::arrive::one.shared::cluster.b64 [%0];" \
        :: "r"((uint32_t)(mbar_smem_addr)) : "memory")
#define TCGEN05_FENCE_AFTER() \
    asm volatile("tcgen05.fence::after_thread_sync;" ::: "memory")
#define TCGEN05_FENCE_BEFORE() \
    asm volatile("tcgen05.fence::before_thread_sync;" ::: "memory")
#define TCGEN05_WAIT_LD() \
    asm volatile("tcgen05.wait::ld.sync.aligned;" ::: "memory")
#define FENCE_ASYNC_SHARED() \
    asm volatile("fence.proxy.async.shared::cta;" ::: "memory")

#define TCGEN05_MMA_TF32(d_tmem, a_desc, b_desc, idesc, enable_d) do { \
    uint32_t _en = (enable_d) ? 1u : 0u; \
    uint32_t _zero = 0u; \
    asm volatile( \
        "{\n\t.reg .pred p;\n\tsetp.ne.u32 p, %6, 0;\n\t" \
        "tcgen05.mma.cta_group::1.kind::tf32 [%0], %1, %2, %3, {%4, %4, %4, %4}, p;\n\t}" \
        :: "r"(d_tmem), "l"(a_desc), "l"(b_desc), "r"(idesc), \
           "r"(_zero), "r"(_zero), "r"(_en) : "memory"); \
} while(0)

#define TCGEN05_LD_32X32B_X32(r, tmem_addr) \
    asm volatile( \
        "tcgen05.ld.sync.aligned.32x32b.x32.b32 " \
        "{%0, %1, %2, %3, %4, %5, %6, %7, " \
        " %8, %9, %10, %11, %12, %13, %14, %15, " \
        " %16, %17, %18, %19, %20, %21, %22, %23, " \
        " %24, %25, %26, %27, %28, %29, %30, %31}, [%32];" \
        : "=r"((r)[0]),  "=r"((r)[1]),  "=r"((r)[2]),  "=r"((r)[3]), \
          "=r"((r)[4]),  "=r"((r)[5]),  "=r"((r)[6]),  "=r"((r)[7]), \
          "=r"((r)[8]),  "=r"((r)[9]),  "=r"((r)[10]), "=r"((r)[11]), \
          "=r"((r)[12]), "=r"((r)[13]), "=r"((r)[14]), "=r"((r)[15]), \
          "=r"((r)[16]), "=r"((r)[17]), "=r"((r)[18]), "=r"((r)[19]), \
          "=r"((r)[20]), "=r"((r)[21]), "=r"((r)[22]), "=r"((r)[23]), \
          "=r"((r)[24]), "=r"((r)[25]), "=r"((r)[26]), "=r"((r)[27]), \
          "=r"((r)[28]), "=r"((r)[29]), "=r"((r)[30]), "=r"((r)[31]) \
        : "r"(tmem_addr))
#endif  // HAS_TCGEN05

#if HAS_TCGEN05
static constexpr uint64_t SMEM_DESC_BASE_SW128 =
    (uint64_t(2)  << 61) | (uint64_t(1) << 46) | (uint64_t(64) << 32) | (uint64_t(1) << 16);
#define MAKE_SMEM_DESC(base_addr) \
    (SMEM_DESC_BASE_SW128 | ((uint64_t)((base_addr) >> 4) & 0x3FFF))
#endif

// idesc: dtype=F32(1<<4), atype=TF32(2<<7), btype=TF32(2<<10), N=128(16<<17), M=128(8<<24)
#define IDESC_TF32 0x08200910u

// -------- tf32 conversion pass: x + 8 weights, segment per blockIdx.y --------
__global__ void cvt_tf32_all(const float* __restrict__ x,
                             const float* __restrict__ Wq, const float* __restrict__ Wk,
                             const float* __restrict__ Wv, const float* __restrict__ Wo,
                             const float* __restrict__ Wfa, const float* __restrict__ Wga,
                             const float* __restrict__ Wfb, const float* __restrict__ Wgb) {
    int seg = blockIdx.y;
    const float* src; float* dst; size_t n;
    switch (seg) {
        case 0: src = x;   dst = g_xtf;          n = (size_t)BT * HIDN; break;
        case 1: src = Wq;  dst = g_wtf + OWQ;    n = 1048576; break;
        case 2: src = Wk;  dst = g_wtf + OWK;    n = 1048576; break;
        case 3: src = Wv;  dst = g_wtf + OWV;    n = 1048576; break;
        case 4: src = Wo;  dst = g_wtf + OWO;    n = 1048576; break;
        case 5: src = Wfa; dst = g_wtf + OWFA;   n = 131072; break;
        case 6: src = Wga; dst = g_wtf + OWGA;   n = 131072; break;
        case 7: src = Wfb; dst = g_wtf + OWFB;   n = 131072; break;
        default: src = Wgb; dst = g_wtf + OWGB;  n = 131072; break;
    }
    size_t i = ((size_t)blockIdx.x * blockDim.x + threadIdx.x) * 4;
    if (i >= n) return;
    float4 v = *(const float4*)(src + i);
    v.x = tf32r(v.x); v.y = tf32r(v.y); v.z = tf32r(v.z); v.w = tf32r(v.w);
    *(float4*)(dst + i) = v;
}

// ============ GEMM: C tile = A[M,K] * W[N,K]^T, 128x128 tiles ============
// Operands are pre-rounded tf32 stored as fp32 — staging is raw cp.async (no cvt).
// grid.z selects weight; A += z*sAz, C += z*sCz. K multiple of 32.
#define CHUNK_BYTES 16384   // 128 rows * 32 fp32 * 4B
__global__ void __launch_bounds__(256, 3)
gemm_tc(const float* __restrict__ A, size_t sAz,
        const float* __restrict__ W0, const float* __restrict__ W1, const float* __restrict__ W2,
        float* __restrict__ C, size_t sCz, int N, int K, int round_out) {
    extern __shared__ char dynraw[];

    const float* W = (blockIdx.z == 0) ? W0 : (blockIdx.z == 1 ? W1 : W2);
    A += sAz * blockIdx.z;
    C += sCz * blockIdx.z;

    int tid = threadIdx.x;
    int bm = blockIdx.y * 128, bn = blockIdx.x * 128;

    uint32_t dynaddr = smem_u32(dynraw);
    uint32_t base = (dynaddr + 1023u) & ~1023u;

#if HAS_TCGEN05
    __shared__ uint32_t tptr_slot;
    __shared__ uint64_t mbar[2];
    uint32_t mb0 = smem_u32(&mbar[0]);
    uint32_t mb1 = smem_u32(&mbar[1]);

    if (tid < 32) {
        TCGEN05_ALLOC(smem_u32(&tptr_slot), 128);
        TCGEN05_RELINQUISH();
    }
    if (tid == 0) { MBARRIER_INIT(mb0, 1); MBARRIER_INIT(mb1, 1); }
    __syncthreads();
    uint32_t tmem = tptr_slot;

    const float* Ag = A + (size_t)bm * K;
    const float* Bg = W + (size_t)bn * K;
    int nk = K >> 5;
    int ph0 = 0, ph1 = 0;

    // prologue: chunk 0 into buf0
    {
        uint32_t a0 = base, b0 = base + CHUNK_BYTES;
#pragma unroll
        for (int u = 0; u < 4; u++) {
            int id = u * 256 + tid;
            int r = id >> 3, s = id & 7;
            uint32_t so = (uint32_t)(r * 128 + ((s ^ (r & 7)) * 16));
            cp16(a0 + so, Ag + (size_t)r * K + s * 4);
            cp16(b0 + so, Bg + (size_t)r * K + s * 4);
        }
        CP_COMMIT();
    }

    for (int kt = 0; kt < nk; kt++) {
        int buf = kt & 1;
        if (kt + 1 < nk) {
            int nbuf = buf ^ 1;
            if (kt >= 1) {  // MMA kt-1 used nbuf; wait before overwrite
                if (nbuf == 0) { MBARRIER_WAIT_PARITY(mb0, ph0); ph0 ^= 1; }
                else           { MBARRIER_WAIT_PARITY(mb1, ph1); ph1 ^= 1; }
            }
            uint32_t an = base + nbuf * (2 * CHUNK_BYTES), bnn = an + CHUNK_BYTES;
            const float* Ak = Ag + (kt + 1) * 32;
            const float* Bk = Bg + (kt + 1) * 32;
#pragma unroll
            for (int u = 0; u < 4; u++) {
                int id = u * 256 + tid;
                int r = id >> 3, s = id & 7;
                uint32_t so = (uint32_t)(r * 128 + ((s ^ (r & 7)) * 16));
                cp16(an + so, Ak + (size_t)r * K + s * 4);
                cp16(bnn + so, Bk + (size_t)r * K + s * 4);
            }
            CP_COMMIT();
            CP_WAIT_1();      // chunk kt complete
        } else {
            CP_WAIT_0();
        }
        FENCE_ASYNC_SHARED();
        __syncthreads();
        if (tid == 0) {
            uint32_t aaddr = base + buf * (2 * CHUNK_BYTES);
            uint64_t ad = MAKE_SMEM_DESC(aaddr);
            uint64_t bd = MAKE_SMEM_DESC(aaddr + CHUNK_BYTES);
#pragma unroll
            for (int s = 0; s < 4; s++)
                TCGEN05_MMA_TF32(tmem, ad + s * 2, bd + s * 2, IDESC_TF32, (kt > 0) || (s > 0));
            TCGEN05_COMMIT((buf == 0) ? mb0 : mb1);
        }
    }
    if (((nk - 1) & 1) == 0) { MBARRIER_WAIT_PARITY(mb0, ph0); }
    else                     { MBARRIER_WAIT_PARITY(mb1, ph1); }
    TCGEN05_FENCE_AFTER();

    // 8-warp epilogue: warps 0-3 cols 0-63, warps 4-7 cols 64-127
    int wid = tid >> 5, lane = tid & 31;
    int m = bm + (wid & 3) * 32 + lane;
    int nbbase = (wid >> 2) * 2;
#pragma unroll
    for (int it = 0; it < 2; it++) {
        int nb = nbbase + it;
        uint32_t r[32];
        TCGEN05_LD_32X32B_X32(r, tmem + nb * 32);
        TCGEN05_WAIT_LD();
        float4* dst = (float4*)&C[(size_t)m * N + bn + nb * 32];
#pragma unroll
        for (int c = 0; c < 8; c++) {
            float4 v = make_float4(__uint_as_float(r[4*c]), __uint_as_float(r[4*c+1]),
                                   __uint_as_float(r[4*c+2]), __uint_as_float(r[4*c+3]));
            if (round_out) { v.x = tf32r(v.x); v.y = tf32r(v.y); v.z = tf32r(v.z); v.w = tf32r(v.w); }
            dst[c] = v;
        }
    }
    TCGEN05_FENCE_BEFORE();
    __syncthreads();
    if (tid < 32) TCGEN05_DEALLOC(tmem, 128);
#else
    // ---------------- SIMT fallback (plain sm_103 target; not expected to run) ----------------
    char* buf_ptr = dynraw + (base - dynaddr);
    float* As = (float*)buf_ptr;
    float* Bs = As + 8 * 128;
    int tx = tid & 15, ty = tid >> 4;
    float acc[8][8];
#pragma unroll
    for (int i = 0; i < 8; i++)
#pragma unroll
        for (int j = 0; j < 8; j++) acc[i][j] = 0.f;

    int nk8 = K >> 3;
    for (int kt = 0; kt < nk8; kt++) {
        __syncthreads();
        {
            int r = tid >> 1, cg = (tid & 1) * 4;
            float4 va = *(const float4*)(A + (size_t)(bm + r) * K + kt * 8 + cg);
            float4 vb = *(const float4*)(W + (size_t)(bn + r) * K + kt * 8 + cg);
            As[(cg + 0) * 128 + r] = va.x; As[(cg + 1) * 128 + r] = va.y;
            As[(cg + 2) * 128 + r] = va.z; As[(cg + 3) * 128 + r] = va.w;
            Bs[(cg + 0) * 128 + r] = vb.x; Bs[(cg + 1) * 128 + r] = vb.y;
            Bs[(cg + 2) * 128 + r] = vb.z; Bs[(cg + 3) * 128 + r] = vb.w;
        }
        __syncthreads();
#pragma unroll
        for (int kk = 0; kk < 8; kk++) {
            float av[8], bv[8];
#pragma unroll
            for (int i = 0; i < 8; i++) av[i] = As[kk * 128 + ty * 8 + i];
#pragma unroll
            for (int j = 0; j < 8; j++) bv[j] = Bs[kk * 128 + tx * 8 + j];
#pragma unroll
            for (int i = 0; i < 8; i++)
#pragma unroll
                for (int j = 0; j < 8; j++)
                    acc[i][j] = fmaf(av[i], bv[j], acc[i][j]);
        }
    }
#pragma unroll
    for (int i = 0; i < 8; i++) {
        int m = bm + ty * 8 + i;
#pragma unroll
        for (int j = 0; j < 8; j++) {
            float v = acc[i][j];
            if (round_out) v = tf32r(v);
            C[(size_t)m * N + bn + tx * 8 + j] = v;
        }
    }
#endif
}

// ---- beta = sigmoid(x @ Wb^T): one warp per (row, head) ----
__global__ void beta_kernel(const float* __restrict__ x, const float* __restrict__ Wb,
                            float* __restrict__ out) {
    int row = blockIdx.x;
    int h = threadIdx.x >> 5;
    int l = threadIdx.x & 31;
    const float* xr = x + (size_t)row * HIDN;
    const float* wr = Wb + (size_t)h * HIDN;
    float acc = 0.f;
#pragma unroll 8
    for (int i = l; i < HIDN; i += 32) acc = fmaf(xr[i], wr[i], acc);
#pragma unroll
    for (int off = 16; off > 0; off >>= 1) acc += __shfl_xor_sync(0xffffffffu, acc, off);
    if (l == 0) out[row * Hh + h] = 1.f / (1.f + expf(-acc));
}

// -------- depthwise causal conv (K=4) + SiLU + optional per-head RMSNorm --------
__global__ void conv_silu_norm(const float* __restrict__ pre_base, const float* __restrict__ wq,
                               const float* __restrict__ wk, const float* __restrict__ wv,
                               float* __restrict__ out_base) {
    int which = blockIdx.y;
    const float* w = (which == 0) ? wq : (which == 1 ? wk : wv);
    const float* pre = pre_base + (size_t)which * BT * HIDN;
    float* out = out_base + (size_t)which * BT * HIDN;
    float postscale = (which == 0) ? (1.f / 128.f) : (which == 1 ? 0.08838834764831845f : 1.f);
    int do_norm = (which < 2);

    int blk = blockIdx.x;
    int h = blk % Hh;
    int bt = blk / Hh;
    int t = bt % Tq;
    int d = threadIdx.x;
    int c = h * Dd + d;

    float acc = 0.f;
#pragma unroll
    for (int j = 0; j < 4; j++) {
        int tt = t - 3 + j;
        if (tt >= 0) acc += pre[(size_t)(bt - t + tt) * HIDN + c] * w[c * 4 + j];
    }
    acc = acc / (1.f + expf(-acc));
    float val = acc;
    if (do_norm) {
        float ss = acc * acc;
#pragma unroll
        for (int off = 16; off > 0; off >>= 1) ss += __shfl_xor_sync(0xffffffffu, ss, off);
        __shared__ float sh[4];
        if ((threadIdx.x & 31) == 0) sh[threadIdx.x >> 5] = ss;
        __syncthreads();
        float tot = sh[0] + sh[1] + sh[2] + sh[3];
        val = acc * rsqrtf(tot * (1.f / 128.f) + 1e-6f) * postscale;
    }
    out[(size_t)bt * HIDN + c] = val;
}

// -------- eg = exp(-exp(A_log[h]) * softplus(a + dt_bias)) --------
__global__ void g_transform(float* __restrict__ a, const float* __restrict__ dt_bias,
                            const float* __restrict__ A_log) {
    int idx = blockIdx.x * blockDim.x + threadIdx.x;
    if (idx >= BT * HIDN) return;
    int c = idx % HIDN;
    int h = c / Dd;
    float x = a[idx] + dt_bias[c];
    float sp = (x > 0.f) ? (x + log1pf(expf(-x))) : log1pf(expf(x));
    a[idx] = expf(-expf(A_log[h]) * sp);
}

// ------- gated delta-rule scan: 16 lanes per Dv column, 8 Dk rows per lane -------
// grid (16 bh, 16 colgroups of 8), 128 threads. Warp owns 2 cols;
// lane: sub = lane>>4 (col), r = lane&15 -> S rows r*8..r*8+7 in registers.
__global__ void __launch_bounds__(128, 2)
scan_kernel(const float* __restrict__ q, const float* __restrict__ k,
            const float* __restrict__ v, const float* __restrict__ eg,
            const float* __restrict__ beta, float* __restrict__ out) {
    int bh = blockIdx.x;
    int b = bh >> 3, h = bh & 7;
    int warp = threadIdx.x >> 5, lane = threadIdx.x & 31;
    int sub = lane >> 4;                    // col within warp (0..1)
    int r = lane & 15;                      // row-group (0..15)
    int col = blockIdx.y * 8 + warp * 2 + sub;
    int rbase = r * 8;
    size_t rowbase = (size_t)b * Tq * HIDN + h * Dd;

    float S[8];
#pragma unroll
    for (int i = 0; i < 8; i++) S[i] = 0.f;

    float4 kc[2], qc[2], ec[2];
    float vc, bc;
    {
#pragma unroll
        for (int ii = 0; ii < 2; ii++) {
            kc[ii] = *(const float4*)(k  + rowbase + rbase + 4 * ii);
            qc[ii] = *(const float4*)(q  + rowbase + rbase + 4 * ii);
            ec[ii] = *(const float4*)(eg + rowbase + rbase + 4 * ii);
        }
        vc = v[rowbase + col];
        bc = beta[(b * Tq) * Hh + h];
    }

    for (int t = 0; t < Tq; t++) {
        size_t row = rowbase + (size_t)t * HIDN;
        float4 kn[2], qn[2], en[2];
        float vn_ = 0.f, bn_ = 0.f;
        if (t + 1 < Tq) {
            size_t rown = row + HIDN;
#pragma unroll
            for (int ii = 0; ii < 2; ii++) {
                kn[ii] = *(const float4*)(k  + rown + rbase + 4 * ii);
                qn[ii] = *(const float4*)(q  + rown + rbase + 4 * ii);
                en[ii] = *(const float4*)(eg + rown + rbase + 4 * ii);
            }
            vn_ = v[rown + col];
            bn_ = beta[(b * Tq + t + 1) * Hh + h];
        }

        // decay + read
        float kv0 = 0.f, kv1 = 0.f, kv2 = 0.f, kv3 = 0.f;
#pragma unroll
        for (int ii = 0; ii < 2; ii++) {
            float s0 = S[4*ii+0] * ec[ii].x; S[4*ii+0] = s0; kv0 = fmaf(kc[ii].x, s0, kv0);
            float s1 = S[4*ii+1] * ec[ii].y; S[4*ii+1] = s1; kv1 = fmaf(kc[ii].y, s1, kv1);
            float s2 = S[4*ii+2] * ec[ii].z; S[4*ii+2] = s2; kv2 = fmaf(kc[ii].z, s2, kv2);
            float s3 = S[4*ii+3] * ec[ii].w; S[4*ii+3] = s3; kv3 = fmaf(kc[ii].w, s3, kv3);
        }
        float kv = (kv0 + kv1) + (kv2 + kv3);
        kv += __shfl_xor_sync(0xffffffffu, kv, 1);
        kv += __shfl_xor_sync(0xffffffffu, kv, 2);
        kv += __shfl_xor_sync(0xffffffffu, kv, 4);
        kv += __shfl_xor_sync(0xffffffffu, kv, 8);
        float delta = bc * (vc - kv);

        // write + output
        float o0 = 0.f, o1 = 0.f, o2 = 0.f, o3 = 0.f;
#pragma unroll
        for (int ii = 0; ii < 2; ii++) {
            float s0 = fmaf(kc[ii].x, delta, S[4*ii+0]); S[4*ii+0] = s0; o0 = fmaf(qc[ii].x, s0, o0);
            float s1 = fmaf(kc[ii].y, delta, S[4*ii+1]); S[4*ii+1] = s1; o1 = fmaf(qc[ii].y, s1, o1);
            float s2 = fmaf(kc[ii].z, delta, S[4*ii+2]); S[4*ii+2] = s2; o2 = fmaf(qc[ii].z, s2, o2);
            float s3 = fmaf(kc[ii].w, delta, S[4*ii+3]); S[4*ii+3] = s3; o3 = fmaf(qc[ii].w, s3, o3);
        }
        float o = (o0 + o1) + (o2 + o3);
        o += __shfl_xor_sync(0xffffffffu, o, 1);
        o += __shfl_xor_sync(0xffffffffu, o, 2);
        o += __shfl_xor_sync(0xffffffffu, o, 4);
        o += __shfl_xor_sync(0xffffffffu, o, 8);
        if (r == 0) out[row + col] = o;

#pragma unroll
        for (int ii = 0; ii < 2; ii++) { kc[ii] = kn[ii]; qc[ii] = qn[ii]; ec[ii] = en[ii]; }
        vc = vn_; bc = bn_;
    }
}

// -------- output RMSNorm * o_norm_w * sigmoid(gate); writes tf32-rounded --------
__global__ void out_norm_gate(float* __restrict__ attn, const float* __restrict__ gate,
                              const float* __restrict__ onw) {
    int blk = blockIdx.x;
    int h = blk % Hh;
    int bt = blk / Hh;
    int d = threadIdx.x;
    size_t idx = (size_t)bt * HIDN + h * Dd + d;
    float val = attn[idx];
    float ss = val * val;
#pragma unroll
    for (int off = 16; off > 0; off >>= 1) ss += __shfl_xor_sync(0xffffffffu, ss, off);
    __shared__ float sh[4];
    if ((threadIdx.x & 31) == 0) sh[threadIdx.x >> 5] = ss;
    __syncthreads();
    float tot = sh[0] + sh[1] + sh[2] + sh[3];
    float gt = gate[idx];
    attn[idx] = tf32r(val * rsqrtf(tot * (1.f / 128.f) + 1e-5f) * onw[d]
              * (1.f / (1.f + expf(-gt))));
}

// ---------------------------------- launch ----------------------------------
extern "C" void kernel_launch(void* const* d_in, const int* in_sizes, int n_in,
                              void* d_out, int out_size) {
    const float* x       = (const float*)d_in[0];
    const float* Wq      = (const float*)d_in[1];
    const float* Wk      = (const float*)d_in[2];
    const float* Wv      = (const float*)d_in[3];
    const float* wq_conv = (const float*)d_in[4];
    const float* wk_conv = (const float*)d_in[5];
    const float* wv_conv = (const float*)d_in[6];
    const float* Wfa     = (const float*)d_in[7];
    const float* Wfb     = (const float*)d_in[8];
    const float* Wb      = (const float*)d_in[9];
    const float* Wga     = (const float*)d_in[10];
    const float* Wgb     = (const float*)d_in[11];
    const float* A_log   = (const float*)d_in[12];
    const float* dt_bias = (const float*)d_in[13];
    const float* onw     = (const float*)d_in[14];
    const float* Wo      = (const float*)d_in[15];
    float* out = (float*)d_out;

    float *pre, *qkvn, *nar, *lr, *betab, *attn, *xtf, *wtf;
    cudaGetSymbolAddress((void**)&pre, g_pre);
    cudaGetSymbolAddress((void**)&qkvn, g_qkvn);
    cudaGetSymbolAddress((void**)&nar, g_nar);
    cudaGetSymbolAddress((void**)&lr, g_lr);
    cudaGetSymbolAddress((void**)&betab, g_betab);
    cudaGetSymbolAddress((void**)&attn, g_attn);
    cudaGetSymbolAddress((void**)&xtf, g_xtf);
    cudaGetSymbolAddress((void**)&wtf, g_wtf);

    const size_t S1 = (size_t)BT * HIDN;
    const size_t SD = (size_t)BT * Dd;
    const int SMEM_GEMM = 4 * CHUNK_BYTES + 1024;   // 66560
    cudaFuncSetAttribute(gemm_tc, cudaFuncAttributeMaxDynamicSharedMemorySize, SMEM_GEMM);

    // tf32 pre-conversion: x + all GEMM weights (RNA, once).
    // seg 0 (x) is BT*HIDN = 2,097,152 elems -> needs 2048 blocks of 256thr x 4elem.
    cvt_tf32_all<<<dim3(2048, 9), 256>>>(x, Wq, Wk, Wv, Wo, Wfa, Wga, Wfb, Wgb);

    // QKV projections (fused via grid.z)
    gemm_tc<<<dim3(8, 16, 3), 256, SMEM_GEMM>>>(xtf, 0, wtf + OWQ, wtf + OWK, wtf + OWV,
                                                pre, S1, HIDN, HIDN, 0);
    // narrow low-rank "a" projections (outputs rounded to tf32 for next GEMM)
    gemm_tc<<<dim3(1, 16, 2), 256, SMEM_GEMM>>>(xtf, 0, wtf + OWFA, wtf + OWGA, wtf + OWGA,
                                                nar, SD, Dd, HIDN, 1);
    // low-rank expansions
    gemm_tc<<<dim3(8, 16, 2), 256, SMEM_GEMM>>>(nar, SD, wtf + OWFB, wtf + OWGB, wtf + OWGB,
                                                lr, S1, HIDN, Dd, 0);
    // beta (on original fp32 x)
    beta_kernel<<<BT, 256>>>(x, Wb, betab);

    // conv + silu (+ head rmsnorm; q: scale^2 = 1/128, k: scale = 1/sqrt(128))
    conv_silu_norm<<<dim3(BT * Hh, 3), 128>>>(pre, wq_conv, wk_conv, wv_conv, qkvn);

    // eg = exp(g) (in place on lr[0])
    g_transform<<<(BT * HIDN + 255) / 256, 256>>>(lr, dt_bias, A_log);

    // recurrence (register-only warp-synchronous scan, 16 lanes/col)
    scan_kernel<<<dim3(16, 16), 128>>>(qkvn, qkvn + S1, qkvn + 2 * S1, lr, betab, attn);

    // output norm/gate (writes tf32-rounded attn) + final projection
    out_norm_gate<<<BT * Hh, 128>>>(attn, lr + S1, onw);
    gemm_tc<<<dim3(8, 16, 1), 256, SMEM_GEMM>>>(attn, 0, wtf + OWO, wtf + OWO, wtf + OWO,
                                                out, 0, HIDN, HIDN, 0);
}